// round 15
// baseline (speedup 1.0000x reference)
#include <cuda_runtime.h>
#include <cuda_fp16.h>
#include <math.h>
#include <stdint.h>

#define E_    32
#define TOPK  4
#define H_    2048
#define I_    1408
#define GS_   128
#define T_    1024
#define ISH_  2816
#define NPAIR (T_*TOPK)

__device__ __forceinline__ int PERM(int i) {
    int r = i & 7;
    return (i & ~7) | (((r & 3) << 1) | (r >> 2));
}

// ---------------- device scratch ----------------
__device__ int    g_counts[E_];
__device__ int    g_offsets[E_];
__device__ int    g_cursor[E_];
__device__ int    g_topk_idx[T_][TOPK];
__device__ float  g_topk_w[T_][TOPK];
__device__ int    g_pair_token[NPAIR];
__device__ float  g_pair_w[NPAIR];
__device__ int    g_pair_pos[T_][TOPK];
__device__ __half g_xh[(size_t)T_ * H_];
__device__ __half g_h[(size_t)NPAIR * I_];
__device__ float  g_y[(size_t)NPAIR * H_];
__device__ __half g_sh[(size_t)T_ * ISH_];
__device__ __half g_sgwT[(size_t)ISH_ * H_];
__device__ __half g_suwT[(size_t)ISH_ * H_];
__device__ __half g_sdwT[(size_t)H_ * ISH_];

// ---------------- helpers ----------------
__device__ __forceinline__ uint32_t smem_u32(const void* p) {
    uint32_t a;
    asm("{ .reg .u64 t; cvta.to.shared.u64 t, %1; cvt.u32.u64 %0, t; }" : "=r"(a) : "l"(p));
    return a;
}
#define CP16(dst, src) asm volatile("cp.async.ca.shared.global [%0], [%1], 16;\n" :: "r"(dst), "l"(src))
#define CP_COMMIT()    asm volatile("cp.async.commit_group;\n" ::: "memory")
#define CP_WAIT0()     asm volatile("cp.async.wait_group 0;\n" ::: "memory")
#define CP_WAIT1()     asm volatile("cp.async.wait_group 1;\n" ::: "memory")

__device__ __forceinline__ uint32_t dq2(uint32_t h, uint32_t z2, uint32_t s2) {
    __half2 r = __hmul2(__hsub2(*(__half2*)&h, *(__half2*)&z2), *(__half2*)&s2);
    return *(uint32_t*)&r;
}
__device__ __forceinline__ uint4 dqw_h(unsigned w, uint32_t z2, uint32_t s2) {
    uint4 v;
    v.x = dq2(( w        & 0x000F000Fu) | 0x64006400u, z2, s2);
    v.y = dq2(((w >> 4 ) & 0x000F000Fu) | 0x64006400u, z2, s2);
    v.z = dq2(((w >> 8 ) & 0x000F000Fu) | 0x64006400u, z2, s2);
    v.w = dq2(((w >> 12) & 0x000F000Fu) | 0x64006400u, z2, s2);
    return v;
}
__device__ __forceinline__ void mk_zs(int z, float s, uint32_t& z2, uint32_t& s2) {
    z2 = 0x64006400u | (unsigned)z | ((unsigned)z << 16);
    unsigned hb = __half_as_ushort(__float2half_rn(s));
    s2 = hb | (hb << 16);
}
__device__ __forceinline__ void mma16(float* d, const uint32_t* a, const uint32_t* b) {
    asm volatile("mma.sync.aligned.m16n8k16.row.col.f32.f16.f16.f32 "
        "{%0,%1,%2,%3},{%4,%5,%6,%7},{%8,%9},{%0,%1,%2,%3};\n"
        : "+f"(d[0]), "+f"(d[1]), "+f"(d[2]), "+f"(d[3])
        : "r"(a[0]), "r"(a[1]), "r"(a[2]), "r"(a[3]), "r"(b[0]), "r"(b[1]));
}
__device__ __forceinline__ float silu_mul(float g, float u) {
    return g / (1.f + __expf(-g)) * u;
}

// ======== expert layout (BM=32/BK=32): buffer = 4608 words = 18KB, 3 buffers
#define BUFE 4608
__device__ __forceinline__ int aoffE(int buf, int kf, int mf, int p) {
    return buf * BUFE + ((kf * 2 + mf) * 4 + p) * 32;
}
__device__ __forceinline__ int boffEgu(int buf, int kf, int sel, int nf, int r) {
    return buf * BUFE + 512 + ((((kf * 2 + sel) * 16 + nf) * 2 + r)) * 32;
}
__device__ __forceinline__ int boffEdn(int buf, int kf, int nf, int r) {
    return buf * BUFE + 512 + ((kf * 32 + nf) * 2 + r) * 32;
}
#define AUXE (3 * BUFE)

// ======== shared layout: buffer = 8192 words, 3 buffers
__device__ __forceinline__ int aoffw(int buf, int kf, int mf, int p) {
    return buf * 8192 + ((kf * 8 + mf) * 4 + p) * 32;
}
__device__ __forceinline__ int boffw_gu(int buf, int kf, int nf, int r, int sel) {
    return buf * 8192 + 4096 + sel * 2048 + ((kf * 8 + nf) * 2 + r) * 32;
}
__device__ __forceinline__ int boffw_dn(int buf, int kf, int nf, int r) {
    return buf * 8192 + 4096 + ((kf * 16 + nf) * 2 + r) * 32;
}
#define SMEM_FUSED ((3 * 8192 + 128) * 4)

#define NSH_GU 352                 // 44 x 8 shared_gu blocks
#define NEX_GU (11 * 32 * 32)      // 11264
#define NSH_DN 128                 // 16 x 8 shared_down blocks
#define NEX_DN (8 * 32 * 32)       // 8192

// ---------------- small kernels ----------------
__global__ void zero_kernel() {
    int i = threadIdx.x;
    if (i < E_) g_counts[i] = 0;
}

__global__ void router_kernel(const float* __restrict__ x, const float* __restrict__ gw) {
    __shared__ float xs[H_];
    __shared__ float part[8][E_];
    __shared__ float scores[E_];
    int t = blockIdx.x;
    for (int h = threadIdx.x; h < H_; h += 256) {
        float v = x[t * H_ + h];
        xs[h] = v;
        g_xh[(size_t)t * H_ + PERM(h)] = __float2half_rn(v);
    }
    __syncthreads();
    int e = threadIdx.x & 31;
    int hh = threadIdx.x >> 5;
    float acc = 0.f;
    for (int h = hh; h < H_; h += 8) acc += xs[h] * gw[h * E_ + e];
    part[hh][e] = acc;
    __syncthreads();
    if (threadIdx.x < E_) {
        float s = 0.f;
        #pragma unroll
        for (int i = 0; i < 8; i++) s += part[i][threadIdx.x];
        scores[threadIdx.x] = 1.f / (1.f + expf(-s));
    }
    __syncthreads();
    if (threadIdx.x == 0) {
        bool used[E_];
        #pragma unroll
        for (int i = 0; i < E_; i++) used[i] = false;
        float v[TOPK]; int id[TOPK];
        float sum = 0.f;
        for (int j = 0; j < TOPK; j++) {
            float best = -1e30f; int bi = 0;
            for (int ee = 0; ee < E_; ee++)
                if (!used[ee] && scores[ee] > best) { best = scores[ee]; bi = ee; }
            used[bi] = true; v[j] = best; id[j] = bi; sum += best;
        }
        float inv = 2.5f / (sum + 1e-20f);
        for (int j = 0; j < TOPK; j++) {
            g_topk_idx[t][j] = id[j];
            g_topk_w[t][j] = v[j] * inv;
            atomicAdd(&g_counts[id[j]], 1);
        }
    }
}

__global__ void scan_scatter_kernel() {
    int tid = threadIdx.x;
    if (tid == 0) {
        int off = 0;
        for (int e = 0; e < E_; e++) {
            g_offsets[e] = off; g_cursor[e] = off; off += g_counts[e];
        }
    }
    __syncthreads();
    int t = tid;
    for (int j = 0; j < TOPK; j++) {
        int e = g_topk_idx[t][j];
        int pos = atomicAdd(&g_cursor[e], 1);
        g_pair_token[pos] = t;
        g_pair_w[pos] = g_topk_w[t][j];
        g_pair_pos[t][j] = pos;
    }
}

// fused transposes of the 3 shared-expert weights (z selects which)
__global__ void transpose3_kernel(const float* __restrict__ sgw, const float* __restrict__ suw,
                                  const float* __restrict__ sdw) {
    __shared__ float tile[32][33];
    int z = blockIdx.z;
    const float* in;
    __half* out;
    int R, C, c0, r0;
    if (z < 2) {
        in = z ? suw : sgw;
        out = z ? g_suwT : g_sgwT;
        R = H_; C = ISH_;
        c0 = blockIdx.x * 32;   // < ISH
        r0 = blockIdx.y * 32;   // < H
    } else {
        in = sdw;
        out = g_sdwT;
        R = ISH_; C = H_;
        c0 = blockIdx.y * 32;   // < H  (64 blocks)
        r0 = blockIdx.x * 32;   // < ISH (88 blocks)
    }
    for (int i = threadIdx.y; i < 32; i += 8)
        tile[i][threadIdx.x] = in[(size_t)(r0 + i) * C + c0 + threadIdx.x];
    __syncthreads();
    for (int i = threadIdx.y; i < 32; i += 8)
        out[(size_t)(c0 + i) * R + PERM(r0 + threadIdx.x)] = __float2half_rn(tile[threadIdx.x][i]);
}

// final combine: out[t] += sum of 4 routed pair rows
__global__ void combine_kernel(float* __restrict__ out) {
    int t = blockIdx.x;
    int p0 = g_pair_pos[t][0], p1 = g_pair_pos[t][1];
    int p2 = g_pair_pos[t][2], p3 = g_pair_pos[t][3];
    const float* y0 = g_y + (size_t)p0 * H_;
    const float* y1 = g_y + (size_t)p1 * H_;
    const float* y2 = g_y + (size_t)p2 * H_;
    const float* y3 = g_y + (size_t)p3 * H_;
    float* orow = out + (size_t)t * H_;
    for (int c = threadIdx.x * 4; c < H_; c += 1024) {
        float4 o = *(float4*)(orow + c);
        float4 a = *(const float4*)(y0 + c);
        float4 b = *(const float4*)(y1 + c);
        float4 d = *(const float4*)(y2 + c);
        float4 e = *(const float4*)(y3 + c);
        o.x += a.x + b.x + d.x + e.x;
        o.y += a.y + b.y + d.y + e.y;
        o.z += a.z + b.z + d.z + e.z;
        o.w += a.w + b.w + d.w + e.w;
        *(float4*)(orow + c) = o;
    }
}

// ================= fused gate/up =================
__global__ __launch_bounds__(256, 2) void fused_gu_mma(
    const int* __restrict__ gq, const int* __restrict__ gz, const float* __restrict__ gs,
    const int* __restrict__ uq, const int* __restrict__ uz, const float* __restrict__ us)
{
    extern __shared__ uint32_t smw[];
    int bid = blockIdx.x;
    int tid = threadIdx.x;
    uint32_t smb = smem_u32(smw);

    if (bid < NSH_GU) {
        // ---------- shared gate/up: block 128M x 64N(per sel) ----------
        int m0 = (bid / 44) * 128;
        int n0 = (bid % 44) * 64;

        int fm = tid & 127, kh = tid >> 7;
        const __half* xrow = g_xh + (size_t)(m0 + fm) * H_ + kh * 32;
        int amf = fm >> 4, ami8 = (fm & 15) >> 3, albA = 4 * (fm & 7);
        uint32_t adst[4];
        #pragma unroll
        for (int gg = 0; gg < 4; gg++)
            adst[gg] = smb + 4 * (aoffw(0, kh * 2 + (gg >> 1), amf, ami8 + 2 * (gg & 1)) + albA);

        int sel = tid >> 7;
        int t2 = tid & 127;
        int fn = t2 & 63, bkh = t2 >> 6;
        const __half* brow = (sel ? g_suwT : g_sgwT) + (size_t)(n0 + fn) * H_ + bkh * 32;
        int bnf = fn >> 3, blbB = 4 * (fn & 7);
        uint32_t bdst[4];
        #pragma unroll
        for (int wi = 0; wi < 4; wi++)
            bdst[wi] = smb + 4 * (boffw_gu(0, bkh * 2 + (wi >> 1), bnf, wi & 1, sel) + blbB);

        int w = tid >> 5, lane = tid & 31;
        int wm = w & 3, wn = w >> 2;

        float accG[2][4][4] = {};
        float accU[2][4][4] = {};

        const int NT = H_ / 64;
        #pragma unroll
        for (int s = 0; s < 2; s++) {
            uint32_t bo = s * 32768;
            #pragma unroll
            for (int gg = 0; gg < 4; gg++) {
                CP16(adst[gg] + bo, xrow + s * 64 + gg * 8);
                CP16(bdst[gg] + bo, brow + s * 64 + gg * 8);
            }
            CP_COMMIT();
        }
        CP_WAIT1();
        __syncthreads();

        int bufc = 0, bufn = 2;
        for (int t = 0; t < NT; t++) {
            if (t + 2 < NT) {
                uint32_t bo = bufn * 32768;
                const __half* xs = xrow + (t + 2) * 64;
                const __half* bs = brow + (t + 2) * 64;
                #pragma unroll
                for (int gg = 0; gg < 4; gg++) {
                    CP16(adst[gg] + bo, xs + gg * 8);
                    CP16(bdst[gg] + bo, bs + gg * 8);
                }
                CP_COMMIT();
            }
            #pragma unroll
            for (int kf = 0; kf < 4; kf++) {
                uint32_t a[2][4], bg[4][2], bu[4][2];
                #pragma unroll
                for (int mf = 0; mf < 2; mf++)
                    #pragma unroll
                    for (int r = 0; r < 4; r++)
                        a[mf][r] = smw[aoffw(bufc, kf, wm * 2 + mf, r) + lane];
                #pragma unroll
                for (int nf = 0; nf < 4; nf++)
                    #pragma unroll
                    for (int r = 0; r < 2; r++) {
                        bg[nf][r] = smw[boffw_gu(bufc, kf, wn * 4 + nf, r, 0) + lane];
                        bu[nf][r] = smw[boffw_gu(bufc, kf, wn * 4 + nf, r, 1) + lane];
                    }
                #pragma unroll
                for (int mf = 0; mf < 2; mf++)
                    #pragma unroll
                    for (int nf = 0; nf < 4; nf++) {
                        mma16(accG[mf][nf], a[mf], bg[nf]);
                        mma16(accU[mf][nf], a[mf], bu[nf]);
                    }
            }
            if (t + 1 < NT) {
                if (t + 2 < NT) CP_WAIT1(); else CP_WAIT0();
            }
            __syncthreads();
            bufc = (bufc == 2) ? 0 : bufc + 1;
            bufn = (bufn == 2) ? 0 : bufn + 1;
        }

        #pragma unroll
        for (int mf = 0; mf < 2; mf++) {
            #pragma unroll
            for (int hh = 0; hh < 2; hh++) {
                int row = wm * 32 + mf * 16 + (lane >> 2) + hh * 8;
                __half* orow = g_sh + (size_t)(m0 + row) * ISH_ + n0;
                #pragma unroll
                for (int nf = 0; nf < 4; nf++) {
                    int col = wn * 32 + nf * 8 + (lane & 3) * 2;
                    float vx = silu_mul(accG[mf][nf][hh * 2],     accU[mf][nf][hh * 2]);
                    float vy = silu_mul(accG[mf][nf][hh * 2 + 1], accU[mf][nf][hh * 2 + 1]);
                    int p = PERM(col);
                    orow[p]     = __float2half_rn(vx);
                    orow[p + 2] = __float2half_rn(vy);
                }
            }
        }
    } else {
        // ---------- expert gate/up: block 32M x 128N(per sel) ----------
        int b = bid - NSH_GU;
        int e = b / 352;
        int r = b % 352;
        int m0 = (r / 11) * 32;
        int n0 = (r % 11) * 128;
        int cnt = g_counts[e];
        if (m0 >= cnt) return;
        int off = g_offsets[e];

        int* toks = (int*)&smw[AUXE];
        if (tid < 32) {
            int m = m0 + tid;
            toks[tid] = (m < cnt) ? g_pair_token[off + m] : 0;
        }
        __syncthreads();

        // A fill (threads 0..127): fm 0..31, gsel 0..3
        int fm = tid & 31, gsel = (tid >> 5) & 3;
        bool afill = tid < 128;
        const __half* xrow = g_xh + (size_t)toks[fm] * H_ + gsel * 8;
        uint32_t adst = smb + 4 * (aoffE(0, gsel >> 1, fm >> 4, ((fm & 15) >> 3) + 2 * (gsel & 1)) + 4 * (fm & 7));
        // B fill: thread owns one (sel, row)
        int sel = tid >> 7, fnl = tid & 127;
        long rowb = (long)e * I_ + n0 + fnl;
        const int4*  qr4 = (const int4*)((sel ? uq : gq) + rowb * (H_ / 8));
        const int*   zr  = (sel ? uz : gz) + rowb * (H_ / GS_);
        const float* sr  = (sel ? us : gs) + rowb * (H_ / GS_);
        int bnf = fnl >> 3, blbB = 4 * (fnl & 7);
        int bwi[4];
        #pragma unroll
        for (int wi = 0; wi < 4; wi++)
            bwi[wi] = boffEgu(0, wi >> 1, sel, bnf, wi & 1) + blbB;

        int wn = tid >> 5, lane = tid & 31;

        float accG[2][2][4] = {};
        float accU[2][2][4] = {};

        const int NT = H_ / 32;  // 64
        int4 pq_c, pq_n; uint32_t zc2, sc2, zn2, sn2;
        {
            uint32_t z02, s02; mk_zs(zr[0], sr[0], z02, s02);
            int4 q0 = qr4[0];
            if (afill) CP16(adst, xrow);
            CP_COMMIT();
            unsigned w0[4] = {(unsigned)q0.x, (unsigned)q0.y, (unsigned)q0.z, (unsigned)q0.w};
            #pragma unroll
            for (int wi = 0; wi < 4; wi++) *(uint4*)&smw[bwi[wi]] = dqw_h(w0[wi], z02, s02);
            int4 q1 = qr4[1];
            if (afill) CP16(adst + BUFE * 4, xrow + 32);
            CP_COMMIT();
            unsigned w1[4] = {(unsigned)q1.x, (unsigned)q1.y, (unsigned)q1.z, (unsigned)q1.w};
            #pragma unroll
            for (int wi = 0; wi < 4; wi++) *(uint4*)&smw[bwi[wi] + BUFE] = dqw_h(w1[wi], z02, s02);
            pq_c = qr4[2]; zc2 = z02; sc2 = s02;
            pq_n = qr4[3]; zn2 = z02; sn2 = s02;
            CP_WAIT1();
            __syncthreads();
        }

        int bufc = 0, bufn = 2;
        for (int t = 0; t < NT; t++) {
            if (t + 2 < NT) {
                uint32_t bo = bufn * (BUFE * 4);
                int wo = bufn * BUFE;
                if (afill) CP16(adst + bo, xrow + (t + 2) * 32);
                CP_COMMIT();
                unsigned wd[4] = {(unsigned)pq_c.x, (unsigned)pq_c.y, (unsigned)pq_c.z, (unsigned)pq_c.w};
                #pragma unroll
                for (int wi = 0; wi < 4; wi++) *(uint4*)&smw[bwi[wi] + wo] = dqw_h(wd[wi], zc2, sc2);
                pq_c = pq_n; zc2 = zn2; sc2 = sn2;
                if (t + 4 < NT) {
                    int gi = (t + 4) >> 2;
                    pq_n = qr4[t + 4]; mk_zs(zr[gi], sr[gi], zn2, sn2);
                }
            }
            #pragma unroll
            for (int kf = 0; kf < 2; kf++) {
                uint32_t a[2][4], bg[2][2], bu[2][2];
                #pragma unroll
                for (int mf = 0; mf < 2; mf++)
                    #pragma unroll
                    for (int r = 0; r < 4; r++)
                        a[mf][r] = smw[aoffE(bufc, kf, mf, r) + lane];
                #pragma unroll
                for (int nf = 0; nf < 2; nf++)
                    #pragma unroll
                    for (int r = 0; r < 2; r++) {
                        bg[nf][r] = smw[boffEgu(bufc, kf, 0, wn * 2 + nf, r) + lane];
                        bu[nf][r] = smw[boffEgu(bufc, kf, 1, wn * 2 + nf, r) + lane];
                    }
                #pragma unroll
                for (int mf = 0; mf < 2; mf++)
                    #pragma unroll
                    for (int nf = 0; nf < 2; nf++) {
                        mma16(accG[mf][nf], a[mf], bg[nf]);
                        mma16(accU[mf][nf], a[mf], bu[nf]);
                    }
            }
            if (t + 1 < NT) {
                if (t + 2 < NT) CP_WAIT1(); else CP_WAIT0();
            }
            __syncthreads();
            bufc = (bufc == 2) ? 0 : bufc + 1;
            bufn = (bufn == 2) ? 0 : bufn + 1;
        }

        #pragma unroll
        for (int mf = 0; mf < 2; mf++) {
            #pragma unroll
            for (int hh = 0; hh < 2; hh++) {
                int row = mf * 16 + (lane >> 2) + hh * 8;
                if (m0 + row < cnt) {
                    __half* orow = g_h + (size_t)(off + m0 + row) * I_ + n0;
                    #pragma unroll
                    for (int nf = 0; nf < 2; nf++) {
                        int col = wn * 16 + nf * 8 + (lane & 3) * 2;
                        float vx = silu_mul(accG[mf][nf][hh * 2],     accU[mf][nf][hh * 2]);
                        float vy = silu_mul(accG[mf][nf][hh * 2 + 1], accU[mf][nf][hh * 2 + 1]);
                        int p = PERM(col);
                        orow[p]     = __float2half_rn(vx);
                        orow[p + 2] = __float2half_rn(vy);
                    }
                }
            }
        }
    }
}

// ================= fused down =================
__global__ __launch_bounds__(256, 2) void fused_dn_mma(
    const int* __restrict__ dq, const int* __restrict__ dz, const float* __restrict__ ds,
    float* __restrict__ out)
{
    extern __shared__ uint32_t smw[];
    int bid = blockIdx.x;
    int tid = threadIdx.x;
    uint32_t smb = smem_u32(smw);

    if (bid < NSH_DN) {
        // ---------- shared down: block 128M x 128N, writes out (no combine) ----------
        int m0 = (bid / 16) * 128;
        int n0 = (bid % 16) * 128;

        int fm = tid & 127, kh = tid >> 7;
        const __half* arow = g_sh + (size_t)(m0 + fm) * ISH_ + kh * 32;
        int amf = fm >> 4, ami8 = (fm & 15) >> 3, albA = 4 * (fm & 7);
        uint32_t adst[4];
        #pragma unroll
        for (int gg = 0; gg < 4; gg++)
            adst[gg] = smb + 4 * (aoffw(0, kh * 2 + (gg >> 1), amf, ami8 + 2 * (gg & 1)) + albA);

        int fn = tid & 127, bkh = tid >> 7;
        const __half* brow = g_sdwT + (size_t)(n0 + fn) * ISH_ + bkh * 32;
        int bnf = fn >> 3, blbB = 4 * (fn & 7);
        uint32_t bdst[4];
        #pragma unroll
        for (int wi = 0; wi < 4; wi++)
            bdst[wi] = smb + 4 * (boffw_dn(0, bkh * 2 + (wi >> 1), bnf, wi & 1) + blbB);

        int w = tid >> 5, lane = tid & 31;
        int wm = w & 1, wn = w >> 1;

        float acc[4][4][4] = {};

        const int NT = ISH_ / 64;  // 44
        #pragma unroll
        for (int s = 0; s < 2; s++) {
            uint32_t bo = s * 32768;
            #pragma unroll
            for (int gg = 0; gg < 4; gg++) {
                CP16(adst[gg] + bo, arow + s * 64 + gg * 8);
                CP16(bdst[gg] + bo, brow + s * 64 + gg * 8);
            }
            CP_COMMIT();
        }
        CP_WAIT1();
        __syncthreads();

        int bufc = 0, bufn = 2;
        for (int t = 0; t < NT; t++) {
            if (t + 2 < NT) {
                uint32_t bo = bufn * 32768;
                const __half* as = arow + (t + 2) * 64;
                const __half* bs = brow + (t + 2) * 64;
                #pragma unroll
                for (int gg = 0; gg < 4; gg++) {
                    CP16(adst[gg] + bo, as + gg * 8);
                    CP16(bdst[gg] + bo, bs + gg * 8);
                }
                CP_COMMIT();
            }
            #pragma unroll
            for (int kf = 0; kf < 4; kf++) {
                uint32_t a[4][4], b[4][2];
                #pragma unroll
                for (int mf = 0; mf < 4; mf++)
                    #pragma unroll
                    for (int r = 0; r < 4; r++)
                        a[mf][r] = smw[aoffw(bufc, kf, wm * 4 + mf, r) + lane];
                #pragma unroll
                for (int nf = 0; nf < 4; nf++)
                    #pragma unroll
                    for (int r = 0; r < 2; r++)
                        b[nf][r] = smw[boffw_dn(bufc, kf, wn * 4 + nf, r) + lane];
                #pragma unroll
                for (int mf = 0; mf < 4; mf++)
                    #pragma unroll
                    for (int nf = 0; nf < 4; nf++)
                        mma16(acc[mf][nf], a[mf], b[nf]);
            }
            if (t + 1 < NT) {
                if (t + 2 < NT) CP_WAIT1(); else CP_WAIT0();
            }
            __syncthreads();
            bufc = (bufc == 2) ? 0 : bufc + 1;
            bufn = (bufn == 2) ? 0 : bufn + 1;
        }

        #pragma unroll
        for (int mf = 0; mf < 4; mf++) {
            #pragma unroll
            for (int hh = 0; hh < 2; hh++) {
                int row = wm * 64 + mf * 16 + (lane >> 2) + hh * 8;
                float* orow = out + (size_t)(m0 + row) * H_ + n0;
                #pragma unroll
                for (int nf = 0; nf < 4; nf++) {
                    int col = wn * 32 + nf * 8 + (lane & 3) * 2;
                    float2 v;
                    v.x = acc[mf][nf][hh * 2];
                    v.y = acc[mf][nf][hh * 2 + 1];
                    *(float2*)(orow + col) = v;
                }
            }
        }
    } else {
        // ---------- expert down: block 32M x 256N ----------
        int b = bid - NSH_DN;
        int e = b / 256;
        int r = b % 256;
        int m0 = (r / 8) * 32;
        int n0 = (r % 8) * 256;
        int cnt = g_counts[e];
        if (m0 >= cnt) return;
        int off = g_offsets[e];

        float* pwv = (float*)&smw[AUXE];
        if (tid < 32) {
            int m = m0 + tid;
            pwv[tid] = (m < cnt) ? g_pair_w[off + m] : 0.f;
        }
        __syncthreads();

        int fm = tid & 31, gsel = (tid >> 5) & 3;
        bool afill = tid < 128;
        size_t ar = (size_t)off + ((m0 + fm < cnt) ? (m0 + fm) : 0);
        const __half* hrow = g_h + ar * I_ + gsel * 8;
        uint32_t adst = smb + 4 * (aoffE(0, gsel >> 1, fm >> 4, ((fm & 15) >> 3) + 2 * (gsel & 1)) + 4 * (fm & 7));

        int fn = tid;
        long rowb = (long)e * H_ + n0 + fn;
        const int4*  qr4 = (const int4*)(dq + rowb * (I_ / 8));
        const int*   zr  = dz + rowb * (I_ / GS_);
        const float* sr  = ds + rowb * (I_ / GS_);
        int bnf = fn >> 3, blbB = 4 * (fn & 7);
        int bwi[4];
        #pragma unroll
        for (int wi = 0; wi < 4; wi++)
            bwi[wi] = boffEdn(0, wi >> 1, bnf, wi & 1) + blbB;

        int wn = tid >> 5, lane = tid & 31;

        float acc[2][4][4] = {};

        const int NT = I_ / 32;  // 44
        int4 pq_c, pq_n; uint32_t zc2, sc2, zn2, sn2;
        {
            uint32_t z02, s02; mk_zs(zr[0], sr[0], z02, s02);
            int4 q0 = qr4[0];
            if (afill) CP16(adst, hrow);
            CP_COMMIT();
            unsigned w0[4] = {(unsigned)q0.x, (unsigned)q0.y, (unsigned)q0.z, (unsigned)q0.w};
            #pragma unroll
            for (int wi = 0; wi < 4; wi++) *(uint4*)&smw[bwi[wi]] = dqw_h(w0[wi], z02, s02);
            int4 q1 = qr4[1];
            if (afill) CP16(adst + BUFE * 4, hrow + 32);
            CP_COMMIT();
            unsigned w1[4] = {(unsigned)q1.x, (unsigned)q1.y, (unsigned)q1.z, (unsigned)q1.w};
            #pragma unroll
            for (int wi = 0; wi < 4; wi++) *(uint4*)&smw[bwi[wi] + BUFE] = dqw_h(w1[wi], z02, s02);
            pq_c = qr4[2]; zc2 = z02; sc2 = s02;
            pq_n = qr4[3]; zn2 = z02; sn2 = s02;
            CP_WAIT1();
            __syncthreads();
        }

        int bufc = 0, bufn = 2;
        for (int t = 0; t < NT; t++) {
            if (t + 2 < NT) {
                uint32_t bo = bufn * (BUFE * 4);
                int wo = bufn * BUFE;
                if (afill) CP16(adst + bo, hrow + (t + 2) * 32);
                CP_COMMIT();
                unsigned wd[4] = {(unsigned)pq_c.x, (unsigned)pq_c.y, (unsigned)pq_c.z, (unsigned)pq_c.w};
                #pragma unroll
                for (int wi = 0; wi < 4; wi++) *(uint4*)&smw[bwi[wi] + wo] = dqw_h(wd[wi], zc2, sc2);
                pq_c = pq_n; zc2 = zn2; sc2 = sn2;
                if (t + 4 < NT) {
                    int gi = (t + 4) >> 2;
                    pq_n = qr4[t + 4]; mk_zs(zr[gi], sr[gi], zn2, sn2);
                }
            }
            #pragma unroll
            for (int kf = 0; kf < 2; kf++) {
                uint32_t a[2][4], b[4][2];
                #pragma unroll
                for (int mf = 0; mf < 2; mf++)
                    #pragma unroll
                    for (int r = 0; r < 4; r++)
                        a[mf][r] = smw[aoffE(bufc, kf, mf, r) + lane];
                #pragma unroll
                for (int nf = 0; nf < 4; nf++)
                    #pragma unroll
                    for (int r = 0; r < 2; r++)
                        b[nf][r] = smw[boffEdn(bufc, kf, wn * 4 + nf, r) + lane];
                #pragma unroll
                for (int mf = 0; mf < 2; mf++)
                    #pragma unroll
                    for (int nf = 0; nf < 4; nf++)
                        mma16(acc[mf][nf], a[mf], b[nf]);
            }
            if (t + 1 < NT) {
                if (t + 2 < NT) CP_WAIT1(); else CP_WAIT0();
            }
            __syncthreads();
            bufc = (bufc == 2) ? 0 : bufc + 1;
            bufn = (bufn == 2) ? 0 : bufn + 1;
        }

        #pragma unroll
        for (int mf = 0; mf < 2; mf++) {
            #pragma unroll
            for (int hh = 0; hh < 2; hh++) {
                int row = mf * 16 + (lane >> 2) + hh * 8;
                if (m0 + row < cnt) {
                    float wgt = pwv[row];
                    float* orow = g_y + (size_t)(off + m0 + row) * H_ + n0;
                    #pragma unroll
                    for (int nf = 0; nf < 4; nf++) {
                        int col = wn * 32 + nf * 8 + (lane & 3) * 2;
                        float2 v;
                        v.x = wgt * acc[mf][nf][hh * 2];
                        v.y = wgt * acc[mf][nf][hh * 2 + 1];
                        *(float2*)(orow + col) = v;
                    }
                }
            }
        }
    }
}

// ---------------- launch ----------------
extern "C" void kernel_launch(void* const* d_in, const int* in_sizes, int n_in,
                              void* d_out, int out_size)
{
    const float* x   = (const float*)d_in[0];
    const float* gw  = (const float*)d_in[1];
    const int*   gq  = (const int*)  d_in[2];
    const int*   gz  = (const int*)  d_in[3];
    const float* gs  = (const float*)d_in[4];
    const int*   uq  = (const int*)  d_in[5];
    const int*   uz  = (const int*)  d_in[6];
    const float* us  = (const float*)d_in[7];
    const int*   dq  = (const int*)  d_in[8];
    const int*   dz  = (const int*)  d_in[9];
    const float* ds  = (const float*)d_in[10];
    const float* sgw = (const float*)d_in[11];
    const float* suw = (const float*)d_in[12];
    const float* sdw = (const float*)d_in[13];
    float* out = (float*)d_out;

    static bool attr_done = false;
    if (!attr_done) {
        cudaFuncSetAttribute(fused_gu_mma, cudaFuncAttributeMaxDynamicSharedMemorySize, SMEM_FUSED);
        cudaFuncSetAttribute(fused_dn_mma, cudaFuncAttributeMaxDynamicSharedMemorySize, SMEM_FUSED);
        attr_done = true;
    }

    zero_kernel<<<1, 32>>>();
    router_kernel<<<T_, 256>>>(x, gw);
    scan_scatter_kernel<<<1, 1024>>>();

    transpose3_kernel<<<dim3(ISH_ / 32, H_ / 32, 3), dim3(32, 8)>>>(sgw, suw, sdw);

    fused_gu_mma<<<NSH_GU + NEX_GU, 256, SMEM_FUSED>>>(gq, gz, gs, uq, uz, us);
    fused_dn_mma<<<NSH_DN + NEX_DN, 256, SMEM_FUSED>>>(dq, dz, ds, out);
    combine_kernel<<<T_, 256>>>(out);
}

// round 16
// speedup vs baseline: 1.2105x; 1.2105x over previous
#include <cuda_runtime.h>
#include <cuda_fp16.h>
#include <math.h>
#include <stdint.h>

#define E_    32
#define TOPK  4
#define H_    2048
#define I_    1408
#define GS_   128
#define T_    1024
#define ISH_  2816
#define NPAIR (T_*TOPK)

__device__ __forceinline__ int PERM(int i) {
    int r = i & 7;
    return (i & ~7) | (((r & 3) << 1) | (r >> 2));
}

// ---------------- device scratch ----------------
__device__ int    g_counts[E_];
__device__ int    g_offsets[E_];
__device__ int    g_cursor[E_];
__device__ int    g_topk_idx[T_][TOPK];
__device__ float  g_topk_w[T_][TOPK];
__device__ int    g_pair_token[NPAIR];
__device__ float  g_pair_w[NPAIR];
__device__ int    g_pair_pos[T_][TOPK];
__device__ __half g_xh[(size_t)T_ * H_];
__device__ __half g_h[(size_t)NPAIR * I_];
__device__ float  g_y[(size_t)NPAIR * H_];
__device__ __half g_sh[(size_t)T_ * ISH_];
__device__ __half g_sgwT[(size_t)ISH_ * H_];
__device__ __half g_suwT[(size_t)ISH_ * H_];
__device__ __half g_sdwT[(size_t)H_ * ISH_];

// ---------------- helpers ----------------
__device__ __forceinline__ uint32_t smem_u32(const void* p) {
    uint32_t a;
    asm("{ .reg .u64 t; cvta.to.shared.u64 t, %1; cvt.u32.u64 %0, t; }" : "=r"(a) : "l"(p));
    return a;
}
#define CP16(dst, src) asm volatile("cp.async.ca.shared.global [%0], [%1], 16;\n" :: "r"(dst), "l"(src))
#define CP_COMMIT()    asm volatile("cp.async.commit_group;\n" ::: "memory")
#define CP_WAIT0()     asm volatile("cp.async.wait_group 0;\n" ::: "memory")
#define CP_WAIT1()     asm volatile("cp.async.wait_group 1;\n" ::: "memory")

__device__ __forceinline__ uint32_t dq2(uint32_t h, uint32_t z2, uint32_t s2) {
    __half2 r = __hmul2(__hsub2(*(__half2*)&h, *(__half2*)&z2), *(__half2*)&s2);
    return *(uint32_t*)&r;
}
__device__ __forceinline__ uint4 dqw_h(unsigned w, uint32_t z2, uint32_t s2) {
    uint4 v;
    v.x = dq2(( w        & 0x000F000Fu) | 0x64006400u, z2, s2);
    v.y = dq2(((w >> 4 ) & 0x000F000Fu) | 0x64006400u, z2, s2);
    v.z = dq2(((w >> 8 ) & 0x000F000Fu) | 0x64006400u, z2, s2);
    v.w = dq2(((w >> 12) & 0x000F000Fu) | 0x64006400u, z2, s2);
    return v;
}
__device__ __forceinline__ void mk_zs(int z, float s, uint32_t& z2, uint32_t& s2) {
    z2 = 0x64006400u | (unsigned)z | ((unsigned)z << 16);
    unsigned hb = __half_as_ushort(__float2half_rn(s));
    s2 = hb | (hb << 16);
}
__device__ __forceinline__ void mma16(float* d, const uint32_t* a, const uint32_t* b) {
    asm volatile("mma.sync.aligned.m16n8k16.row.col.f32.f16.f16.f32 "
        "{%0,%1,%2,%3},{%4,%5,%6,%7},{%8,%9},{%0,%1,%2,%3};\n"
        : "+f"(d[0]), "+f"(d[1]), "+f"(d[2]), "+f"(d[3])
        : "r"(a[0]), "r"(a[1]), "r"(a[2]), "r"(a[3]), "r"(b[0]), "r"(b[1]));
}
__device__ __forceinline__ float silu_mul(float g, float u) {
    return g / (1.f + __expf(-g)) * u;
}

// ======== expert layout (BM=64/BK=32): buffer = 5120 words, 3 buffers
#define BUFW3 5120
__device__ __forceinline__ int aoff3(int buf, int kf, int mf, int p) {
    return buf * BUFW3 + ((kf * 4 + mf) * 4 + p) * 32;
}
__device__ __forceinline__ int boff3gu(int buf, int kf, int sel, int nf, int r) {
    return buf * BUFW3 + 1024 + ((((kf * 2 + sel) * 16 + nf) * 2 + r)) * 32;
}
__device__ __forceinline__ int boff3dn(int buf, int kf, int nf, int r) {
    return buf * BUFW3 + 1024 + ((kf * 32 + nf) * 2 + r) * 32;
}
#define AUX3 (3 * BUFW3)

// ======== shared layout: buffer = 8192 words, 3 buffers
__device__ __forceinline__ int aoffw(int buf, int kf, int mf, int p) {
    return buf * 8192 + ((kf * 8 + mf) * 4 + p) * 32;
}
__device__ __forceinline__ int boffw_gu(int buf, int kf, int nf, int r, int sel) {
    return buf * 8192 + 4096 + sel * 2048 + ((kf * 8 + nf) * 2 + r) * 32;
}
__device__ __forceinline__ int boffw_dn(int buf, int kf, int nf, int r) {
    return buf * 8192 + 4096 + ((kf * 16 + nf) * 2 + r) * 32;
}
#define SMEM_FUSED ((3 * 8192 + 128) * 4)

#define NSH_GU 352   // 44 x 8 shared_gu blocks
#define NEX_GU (11 * 16 * 32)
#define NSH_DN 128   // 16 x 8 shared_down blocks
#define NEX_DN (8 * 16 * 32)

// ---------------- small kernels ----------------
__global__ void zero_kernel() {
    int i = threadIdx.x;
    if (i < E_) g_counts[i] = 0;
}

__global__ void router_kernel(const float* __restrict__ x, const float* __restrict__ gw) {
    __shared__ float xs[H_];
    __shared__ float part[8][E_];
    __shared__ float scores[E_];
    int t = blockIdx.x;
    for (int h = threadIdx.x; h < H_; h += 256) {
        float v = x[t * H_ + h];
        xs[h] = v;
        g_xh[(size_t)t * H_ + PERM(h)] = __float2half_rn(v);
    }
    __syncthreads();
    int e = threadIdx.x & 31;
    int hh = threadIdx.x >> 5;
    float acc = 0.f;
    for (int h = hh; h < H_; h += 8) acc += xs[h] * gw[h * E_ + e];
    part[hh][e] = acc;
    __syncthreads();
    if (threadIdx.x < E_) {
        float s = 0.f;
        #pragma unroll
        for (int i = 0; i < 8; i++) s += part[i][threadIdx.x];
        scores[threadIdx.x] = 1.f / (1.f + expf(-s));
    }
    __syncthreads();
    if (threadIdx.x == 0) {
        bool used[E_];
        #pragma unroll
        for (int i = 0; i < E_; i++) used[i] = false;
        float v[TOPK]; int id[TOPK];
        float sum = 0.f;
        for (int j = 0; j < TOPK; j++) {
            float best = -1e30f; int bi = 0;
            for (int ee = 0; ee < E_; ee++)
                if (!used[ee] && scores[ee] > best) { best = scores[ee]; bi = ee; }
            used[bi] = true; v[j] = best; id[j] = bi; sum += best;
        }
        float inv = 2.5f / (sum + 1e-20f);
        for (int j = 0; j < TOPK; j++) {
            g_topk_idx[t][j] = id[j];
            g_topk_w[t][j] = v[j] * inv;
            atomicAdd(&g_counts[id[j]], 1);
        }
    }
}

__global__ void scan_scatter_kernel() {
    int tid = threadIdx.x;
    if (tid == 0) {
        int off = 0;
        for (int e = 0; e < E_; e++) {
            g_offsets[e] = off; g_cursor[e] = off; off += g_counts[e];
        }
    }
    __syncthreads();
    int t = tid;
    for (int j = 0; j < TOPK; j++) {
        int e = g_topk_idx[t][j];
        int pos = atomicAdd(&g_cursor[e], 1);
        g_pair_token[pos] = t;
        g_pair_w[pos] = g_topk_w[t][j];
        g_pair_pos[t][j] = pos;
    }
}

__global__ void transpose_half(const float* __restrict__ in, __half* __restrict__ out, int R, int C) {
    __shared__ float tile[32][33];
    int c0 = blockIdx.x * 32, r0 = blockIdx.y * 32;
    for (int i = threadIdx.y; i < 32; i += 8)
        tile[i][threadIdx.x] = in[(size_t)(r0 + i) * C + c0 + threadIdx.x];
    __syncthreads();
    for (int i = threadIdx.y; i < 32; i += 8)
        out[(size_t)(c0 + i) * R + PERM(r0 + threadIdx.x)] = __float2half_rn(tile[threadIdx.x][i]);
}

// final combine: out[t] += sum of 4 routed pair rows
__global__ void combine_kernel(float* __restrict__ out) {
    int t = blockIdx.x;
    int p0 = g_pair_pos[t][0], p1 = g_pair_pos[t][1];
    int p2 = g_pair_pos[t][2], p3 = g_pair_pos[t][3];
    const float* y0 = g_y + (size_t)p0 * H_;
    const float* y1 = g_y + (size_t)p1 * H_;
    const float* y2 = g_y + (size_t)p2 * H_;
    const float* y3 = g_y + (size_t)p3 * H_;
    float* orow = out + (size_t)t * H_;
    for (int c = threadIdx.x * 4; c < H_; c += 1024) {
        float4 o = *(float4*)(orow + c);
        float4 a = *(const float4*)(y0 + c);
        float4 b = *(const float4*)(y1 + c);
        float4 d = *(const float4*)(y2 + c);
        float4 e = *(const float4*)(y3 + c);
        o.x += a.x + b.x + d.x + e.x;
        o.y += a.y + b.y + d.y + e.y;
        o.z += a.z + b.z + d.z + e.z;
        o.w += a.w + b.w + d.w + e.w;
        *(float4*)(orow + c) = o;
    }
}

// ================= fused gate/up =================
__global__ __launch_bounds__(256, 2) void fused_gu_mma(
    const int* __restrict__ gq, const int* __restrict__ gz, const float* __restrict__ gs,
    const int* __restrict__ uq, const int* __restrict__ uz, const float* __restrict__ us)
{
    extern __shared__ uint32_t smw[];
    int bid = blockIdx.x;
    int tid = threadIdx.x;
    uint32_t smb = smem_u32(smw);

    if (bid < NSH_GU) {
        // ---------- shared gate/up: block 128M x 64N(per sel) ----------
        int m0 = (bid / 44) * 128;
        int n0 = (bid % 44) * 64;

        int fm = tid & 127, kh = tid >> 7;
        const __half* xrow = g_xh + (size_t)(m0 + fm) * H_ + kh * 32;
        int amf = fm >> 4, ami8 = (fm & 15) >> 3, albA = 4 * (fm & 7);
        uint32_t adst[4];
        #pragma unroll
        for (int gg = 0; gg < 4; gg++)
            adst[gg] = smb + 4 * (aoffw(0, kh * 2 + (gg >> 1), amf, ami8 + 2 * (gg & 1)) + albA);

        int sel = tid >> 7;
        int t2 = tid & 127;
        int fn = t2 & 63, bkh = t2 >> 6;
        const __half* brow = (sel ? g_suwT : g_sgwT) + (size_t)(n0 + fn) * H_ + bkh * 32;
        int bnf = fn >> 3, blbB = 4 * (fn & 7);
        uint32_t bdst[4];
        #pragma unroll
        for (int wi = 0; wi < 4; wi++)
            bdst[wi] = smb + 4 * (boffw_gu(0, bkh * 2 + (wi >> 1), bnf, wi & 1, sel) + blbB);

        int w = tid >> 5, lane = tid & 31;
        int wm = w & 3, wn = w >> 2;

        float accG[2][4][4] = {};
        float accU[2][4][4] = {};

        const int NT = H_ / 64;
        #pragma unroll
        for (int s = 0; s < 2; s++) {
            uint32_t bo = s * 32768;
            #pragma unroll
            for (int gg = 0; gg < 4; gg++) {
                CP16(adst[gg] + bo, xrow + s * 64 + gg * 8);
                CP16(bdst[gg] + bo, brow + s * 64 + gg * 8);
            }
            CP_COMMIT();
        }
        CP_WAIT1();
        __syncthreads();

        int bufc = 0, bufn = 2;
        for (int t = 0; t < NT; t++) {
            if (t + 2 < NT) {
                uint32_t bo = bufn * 32768;
                const __half* xs = xrow + (t + 2) * 64;
                const __half* bs = brow + (t + 2) * 64;
                #pragma unroll
                for (int gg = 0; gg < 4; gg++) {
                    CP16(adst[gg] + bo, xs + gg * 8);
                    CP16(bdst[gg] + bo, bs + gg * 8);
                }
                CP_COMMIT();
            }
            #pragma unroll
            for (int kf = 0; kf < 4; kf++) {
                uint32_t a[2][4], bg[4][2], bu[4][2];
                #pragma unroll
                for (int mf = 0; mf < 2; mf++)
                    #pragma unroll
                    for (int r = 0; r < 4; r++)
                        a[mf][r] = smw[aoffw(bufc, kf, wm * 2 + mf, r) + lane];
                #pragma unroll
                for (int nf = 0; nf < 4; nf++)
                    #pragma unroll
                    for (int r = 0; r < 2; r++) {
                        bg[nf][r] = smw[boffw_gu(bufc, kf, wn * 4 + nf, r, 0) + lane];
                        bu[nf][r] = smw[boffw_gu(bufc, kf, wn * 4 + nf, r, 1) + lane];
                    }
                #pragma unroll
                for (int mf = 0; mf < 2; mf++)
                    #pragma unroll
                    for (int nf = 0; nf < 4; nf++) {
                        mma16(accG[mf][nf], a[mf], bg[nf]);
                        mma16(accU[mf][nf], a[mf], bu[nf]);
                    }
            }
            if (t + 1 < NT) {
                if (t + 2 < NT) CP_WAIT1(); else CP_WAIT0();
            }
            __syncthreads();
            bufc = (bufc == 2) ? 0 : bufc + 1;
            bufn = (bufn == 2) ? 0 : bufn + 1;
        }

        #pragma unroll
        for (int mf = 0; mf < 2; mf++) {
            #pragma unroll
            for (int hh = 0; hh < 2; hh++) {
                int row = wm * 32 + mf * 16 + (lane >> 2) + hh * 8;
                __half* orow = g_sh + (size_t)(m0 + row) * ISH_ + n0;
                #pragma unroll
                for (int nf = 0; nf < 4; nf++) {
                    int col = wn * 32 + nf * 8 + (lane & 3) * 2;
                    float vx = silu_mul(accG[mf][nf][hh * 2],     accU[mf][nf][hh * 2]);
                    float vy = silu_mul(accG[mf][nf][hh * 2 + 1], accU[mf][nf][hh * 2 + 1]);
                    int p = PERM(col);
                    orow[p]     = __float2half_rn(vx);
                    orow[p + 2] = __float2half_rn(vy);
                }
            }
        }
    } else {
        // ---------- expert gate/up: block 64M x 128N(per sel) ----------
        int b = bid - NSH_GU;
        int e = b / 176;
        int r = b % 176;
        int m0 = (r / 11) * 64;
        int n0 = (r % 11) * 128;
        int cnt = g_counts[e];
        if (m0 >= cnt) return;
        int off = g_offsets[e];

        int* toks = (int*)&smw[AUX3];
        if (tid < 64) {
            int m = m0 + tid;
            toks[tid] = (m < cnt) ? g_pair_token[off + m] : 0;
        }
        __syncthreads();

        int fm = tid & 63, gsel = tid >> 6;
        const __half* xrow = g_xh + (size_t)toks[fm] * H_ + gsel * 8;
        uint32_t adst = smb + 4 * (aoff3(0, gsel >> 1, fm >> 4, ((fm & 15) >> 3) + 2 * (gsel & 1)) + 4 * (fm & 7));
        int sel = tid >> 7, fnl = tid & 127;
        long rowb = (long)e * I_ + n0 + fnl;
        const int4*  qr4 = (const int4*)((sel ? uq : gq) + rowb * (H_ / 8));
        const int*   zr  = (sel ? uz : gz) + rowb * (H_ / GS_);
        const float* sr  = (sel ? us : gs) + rowb * (H_ / GS_);
        int bnf = fnl >> 3, blbB = 4 * (fnl & 7);
        int bwi[4];
        #pragma unroll
        for (int wi = 0; wi < 4; wi++)
            bwi[wi] = boff3gu(0, wi >> 1, sel, bnf, wi & 1) + blbB;

        int wn = tid >> 5, lane = tid & 31;

        float accG[4][2][4] = {};
        float accU[4][2][4] = {};

        const int NT = H_ / 32;  // 64
        int4 pq_c, pq_n; uint32_t zc2, sc2, zn2, sn2;
        {
            uint32_t z02, s02; mk_zs(zr[0], sr[0], z02, s02);
            int4 q0 = qr4[0];
            CP16(adst, xrow); CP_COMMIT();
            unsigned w0[4] = {(unsigned)q0.x, (unsigned)q0.y, (unsigned)q0.z, (unsigned)q0.w};
            #pragma unroll
            for (int wi = 0; wi < 4; wi++) *(uint4*)&smw[bwi[wi]] = dqw_h(w0[wi], z02, s02);
            int4 q1 = qr4[1];
            CP16(adst + BUFW3 * 4, xrow + 32); CP_COMMIT();
            unsigned w1[4] = {(unsigned)q1.x, (unsigned)q1.y, (unsigned)q1.z, (unsigned)q1.w};
            #pragma unroll
            for (int wi = 0; wi < 4; wi++) *(uint4*)&smw[bwi[wi] + BUFW3] = dqw_h(w1[wi], z02, s02);
            pq_c = qr4[2]; zc2 = z02; sc2 = s02;
            pq_n = qr4[3]; zn2 = z02; sn2 = s02;
            CP_WAIT1();
            __syncthreads();
        }

        int bufc = 0, bufn = 2;
        for (int t = 0; t < NT; t++) {
            if (t + 2 < NT) {
                uint32_t bo = bufn * (BUFW3 * 4);
                int wo = bufn * BUFW3;
                CP16(adst + bo, xrow + (t + 2) * 32); CP_COMMIT();
                unsigned wd[4] = {(unsigned)pq_c.x, (unsigned)pq_c.y, (unsigned)pq_c.z, (unsigned)pq_c.w};
                #pragma unroll
                for (int wi = 0; wi < 4; wi++) *(uint4*)&smw[bwi[wi] + wo] = dqw_h(wd[wi], zc2, sc2);
                pq_c = pq_n; zc2 = zn2; sc2 = sn2;
                if (t + 4 < NT) {
                    int gi = (t + 4) >> 2;
                    pq_n = qr4[t + 4]; mk_zs(zr[gi], sr[gi], zn2, sn2);
                }
            }
            #pragma unroll
            for (int kf = 0; kf < 2; kf++) {
                uint32_t a[4][4], bg[2][2], bu[2][2];
                #pragma unroll
                for (int mf = 0; mf < 4; mf++)
                    #pragma unroll
                    for (int r = 0; r < 4; r++)
                        a[mf][r] = smw[aoff3(bufc, kf, mf, r) + lane];
                #pragma unroll
                for (int nf = 0; nf < 2; nf++)
                    #pragma unroll
                    for (int r = 0; r < 2; r++) {
                        bg[nf][r] = smw[boff3gu(bufc, kf, 0, wn * 2 + nf, r) + lane];
                        bu[nf][r] = smw[boff3gu(bufc, kf, 1, wn * 2 + nf, r) + lane];
                    }
                #pragma unroll
                for (int mf = 0; mf < 4; mf++)
                    #pragma unroll
                    for (int nf = 0; nf < 2; nf++) {
                        mma16(accG[mf][nf], a[mf], bg[nf]);
                        mma16(accU[mf][nf], a[mf], bu[nf]);
                    }
            }
            if (t + 1 < NT) {
                if (t + 2 < NT) CP_WAIT1(); else CP_WAIT0();
            }
            __syncthreads();
            bufc = (bufc == 2) ? 0 : bufc + 1;
            bufn = (bufn == 2) ? 0 : bufn + 1;
        }

        #pragma unroll
        for (int mf = 0; mf < 4; mf++) {
            #pragma unroll
            for (int hh = 0; hh < 2; hh++) {
                int row = mf * 16 + (lane >> 2) + hh * 8;
                if (m0 + row < cnt) {
                    __half* orow = g_h + (size_t)(off + m0 + row) * I_ + n0;
                    #pragma unroll
                    for (int nf = 0; nf < 2; nf++) {
                        int col = wn * 16 + nf * 8 + (lane & 3) * 2;
                        float vx = silu_mul(accG[mf][nf][hh * 2],     accU[mf][nf][hh * 2]);
                        float vy = silu_mul(accG[mf][nf][hh * 2 + 1], accU[mf][nf][hh * 2 + 1]);
                        int p = PERM(col);
                        orow[p]     = __float2half_rn(vx);
                        orow[p + 2] = __float2half_rn(vy);
                    }
                }
            }
        }
    }
}

// ================= fused down =================
__global__ __launch_bounds__(256, 2) void fused_dn_mma(
    const int* __restrict__ dq, const int* __restrict__ dz, const float* __restrict__ ds,
    float* __restrict__ out)
{
    extern __shared__ uint32_t smw[];
    int bid = blockIdx.x;
    int tid = threadIdx.x;
    uint32_t smb = smem_u32(smw);

    if (bid < NSH_DN) {
        // ---------- shared down: block 128M x 128N, writes out (no combine) ----------
        int m0 = (bid / 16) * 128;
        int n0 = (bid % 16) * 128;

        int fm = tid & 127, kh = tid >> 7;
        const __half* arow = g_sh + (size_t)(m0 + fm) * ISH_ + kh * 32;
        int amf = fm >> 4, ami8 = (fm & 15) >> 3, albA = 4 * (fm & 7);
        uint32_t adst[4];
        #pragma unroll
        for (int gg = 0; gg < 4; gg++)
            adst[gg] = smb + 4 * (aoffw(0, kh * 2 + (gg >> 1), amf, ami8 + 2 * (gg & 1)) + albA);

        int fn = tid & 127, bkh = tid >> 7;
        const __half* brow = g_sdwT + (size_t)(n0 + fn) * ISH_ + bkh * 32;
        int bnf = fn >> 3, blbB = 4 * (fn & 7);
        uint32_t bdst[4];
        #pragma unroll
        for (int wi = 0; wi < 4; wi++)
            bdst[wi] = smb + 4 * (boffw_dn(0, bkh * 2 + (wi >> 1), bnf, wi & 1) + blbB);

        int w = tid >> 5, lane = tid & 31;
        int wm = w & 1, wn = w >> 1;

        float acc[4][4][4] = {};

        const int NT = ISH_ / 64;  // 44
        #pragma unroll
        for (int s = 0; s < 2; s++) {
            uint32_t bo = s * 32768;
            #pragma unroll
            for (int gg = 0; gg < 4; gg++) {
                CP16(adst[gg] + bo, arow + s * 64 + gg * 8);
                CP16(bdst[gg] + bo, brow + s * 64 + gg * 8);
            }
            CP_COMMIT();
        }
        CP_WAIT1();
        __syncthreads();

        int bufc = 0, bufn = 2;
        for (int t = 0; t < NT; t++) {
            if (t + 2 < NT) {
                uint32_t bo = bufn * 32768;
                const __half* as = arow + (t + 2) * 64;
                const __half* bs = brow + (t + 2) * 64;
                #pragma unroll
                for (int gg = 0; gg < 4; gg++) {
                    CP16(adst[gg] + bo, as + gg * 8);
                    CP16(bdst[gg] + bo, bs + gg * 8);
                }
                CP_COMMIT();
            }
            #pragma unroll
            for (int kf = 0; kf < 4; kf++) {
                uint32_t a[4][4], b[4][2];
                #pragma unroll
                for (int mf = 0; mf < 4; mf++)
                    #pragma unroll
                    for (int r = 0; r < 4; r++)
                        a[mf][r] = smw[aoffw(bufc, kf, wm * 4 + mf, r) + lane];
                #pragma unroll
                for (int nf = 0; nf < 4; nf++)
                    #pragma unroll
                    for (int r = 0; r < 2; r++)
                        b[nf][r] = smw[boffw_dn(bufc, kf, wn * 4 + nf, r) + lane];
                #pragma unroll
                for (int mf = 0; mf < 4; mf++)
                    #pragma unroll
                    for (int nf = 0; nf < 4; nf++)
                        mma16(acc[mf][nf], a[mf], b[nf]);
            }
            if (t + 1 < NT) {
                if (t + 2 < NT) CP_WAIT1(); else CP_WAIT0();
            }
            __syncthreads();
            bufc = (bufc == 2) ? 0 : bufc + 1;
            bufn = (bufn == 2) ? 0 : bufn + 1;
        }

        #pragma unroll
        for (int mf = 0; mf < 4; mf++) {
            #pragma unroll
            for (int hh = 0; hh < 2; hh++) {
                int row = wm * 64 + mf * 16 + (lane >> 2) + hh * 8;
                float* orow = out + (size_t)(m0 + row) * H_ + n0;
                #pragma unroll
                for (int nf = 0; nf < 4; nf++) {
                    int col = wn * 32 + nf * 8 + (lane & 3) * 2;
                    float2 v;
                    v.x = acc[mf][nf][hh * 2];
                    v.y = acc[mf][nf][hh * 2 + 1];
                    *(float2*)(orow + col) = v;
                }
            }
        }
    } else {
        // ---------- expert down: block 64M x 256N ----------
        int b = bid - NSH_DN;
        int e = b / 128;
        int r = b % 128;
        int m0 = (r / 8) * 64;
        int n0 = (r % 8) * 256;
        int cnt = g_counts[e];
        if (m0 >= cnt) return;
        int off = g_offsets[e];

        float* pwv = (float*)&smw[AUX3];
        if (tid < 64) {
            int m = m0 + tid;
            pwv[tid] = (m < cnt) ? g_pair_w[off + m] : 0.f;
        }
        __syncthreads();

        int fm = tid & 63, gsel = tid >> 6;
        size_t ar = (size_t)off + ((m0 + fm < cnt) ? (m0 + fm) : 0);
        const __half* hrow = g_h + ar * I_ + gsel * 8;
        uint32_t adst = smb + 4 * (aoff3(0, gsel >> 1, fm >> 4, ((fm & 15) >> 3) + 2 * (gsel & 1)) + 4 * (fm & 7));

        int fn = tid;
        long rowb = (long)e * H_ + n0 + fn;
        const int4*  qr4 = (const int4*)(dq + rowb * (I_ / 8));
        const int*   zr  = dz + rowb * (I_ / GS_);
        const float* sr  = ds + rowb * (I_ / GS_);
        int bnf = fn >> 3, blbB = 4 * (fn & 7);
        int bwi[4];
        #pragma unroll
        for (int wi = 0; wi < 4; wi++)
            bwi[wi] = boff3dn(0, wi >> 1, bnf, wi & 1) + blbB;

        int wn = tid >> 5, lane = tid & 31;

        float acc[4][4][4] = {};

        const int NT = I_ / 32;  // 44
        int4 pq_c, pq_n; uint32_t zc2, sc2, zn2, sn2;
        {
            uint32_t z02, s02; mk_zs(zr[0], sr[0], z02, s02);
            int4 q0 = qr4[0];
            CP16(adst, hrow); CP_COMMIT();
            unsigned w0[4] = {(unsigned)q0.x, (unsigned)q0.y, (unsigned)q0.z, (unsigned)q0.w};
            #pragma unroll
            for (int wi = 0; wi < 4; wi++) *(uint4*)&smw[bwi[wi]] = dqw_h(w0[wi], z02, s02);
            int4 q1 = qr4[1];
            CP16(adst + BUFW3 * 4, hrow + 32); CP_COMMIT();
            unsigned w1[4] = {(unsigned)q1.x, (unsigned)q1.y, (unsigned)q1.z, (unsigned)q1.w};
            #pragma unroll
            for (int wi = 0; wi < 4; wi++) *(uint4*)&smw[bwi[wi] + BUFW3] = dqw_h(w1[wi], z02, s02);
            pq_c = qr4[2]; zc2 = z02; sc2 = s02;
            pq_n = qr4[3]; zn2 = z02; sn2 = s02;
            CP_WAIT1();
            __syncthreads();
        }

        int bufc = 0, bufn = 2;
        for (int t = 0; t < NT; t++) {
            if (t + 2 < NT) {
                uint32_t bo = bufn * (BUFW3 * 4);
                int wo = bufn * BUFW3;
                CP16(adst + bo, hrow + (t + 2) * 32); CP_COMMIT();
                unsigned wd[4] = {(unsigned)pq_c.x, (unsigned)pq_c.y, (unsigned)pq_c.z, (unsigned)pq_c.w};
                #pragma unroll
                for (int wi = 0; wi < 4; wi++) *(uint4*)&smw[bwi[wi] + wo] = dqw_h(wd[wi], zc2, sc2);
                pq_c = pq_n; zc2 = zn2; sc2 = sn2;
                if (t + 4 < NT) {
                    int gi = (t + 4) >> 2;
                    pq_n = qr4[t + 4]; mk_zs(zr[gi], sr[gi], zn2, sn2);
                }
            }
            #pragma unroll
            for (int kf = 0; kf < 2; kf++) {
                uint32_t a[4][4], b[4][2];
                #pragma unroll
                for (int mf = 0; mf < 4; mf++)
                    #pragma unroll
                    for (int r = 0; r < 4; r++)
                        a[mf][r] = smw[aoff3(bufc, kf, mf, r) + lane];
                #pragma unroll
                for (int nf = 0; nf < 4; nf++)
                    #pragma unroll
                    for (int r = 0; r < 2; r++)
                        b[nf][r] = smw[boff3dn(bufc, kf, wn * 4 + nf, r) + lane];
                #pragma unroll
                for (int mf = 0; mf < 4; mf++)
                    #pragma unroll
                    for (int nf = 0; nf < 4; nf++)
                        mma16(acc[mf][nf], a[mf], b[nf]);
            }
            if (t + 1 < NT) {
                if (t + 2 < NT) CP_WAIT1(); else CP_WAIT0();
            }
            __syncthreads();
            bufc = (bufc == 2) ? 0 : bufc + 1;
            bufn = (bufn == 2) ? 0 : bufn + 1;
        }

        #pragma unroll
        for (int mf = 0; mf < 4; mf++) {
            #pragma unroll
            for (int hh = 0; hh < 2; hh++) {
                int row = mf * 16 + (lane >> 2) + hh * 8;
                if (m0 + row < cnt) {
                    float wgt = pwv[row];
                    float* orow = g_y + (size_t)(off + m0 + row) * H_ + n0;
                    #pragma unroll
                    for (int nf = 0; nf < 4; nf++) {
                        int col = wn * 32 + nf * 8 + (lane & 3) * 2;
                        float2 v;
                        v.x = wgt * acc[mf][nf][hh * 2];
                        v.y = wgt * acc[mf][nf][hh * 2 + 1];
                        *(float2*)(orow + col) = v;
                    }
                }
            }
        }
    }
}

// ---------------- launch ----------------
extern "C" void kernel_launch(void* const* d_in, const int* in_sizes, int n_in,
                              void* d_out, int out_size)
{
    const float* x   = (const float*)d_in[0];
    const float* gw  = (const float*)d_in[1];
    const int*   gq  = (const int*)  d_in[2];
    const int*   gz  = (const int*)  d_in[3];
    const float* gs  = (const float*)d_in[4];
    const int*   uq  = (const int*)  d_in[5];
    const int*   uz  = (const int*)  d_in[6];
    const float* us  = (const float*)d_in[7];
    const int*   dq  = (const int*)  d_in[8];
    const int*   dz  = (const int*)  d_in[9];
    const float* ds  = (const float*)d_in[10];
    const float* sgw = (const float*)d_in[11];
    const float* suw = (const float*)d_in[12];
    const float* sdw = (const float*)d_in[13];
    float* out = (float*)d_out;

    static bool attr_done = false;
    if (!attr_done) {
        cudaFuncSetAttribute(fused_gu_mma, cudaFuncAttributeMaxDynamicSharedMemorySize, SMEM_FUSED);
        cudaFuncSetAttribute(fused_dn_mma, cudaFuncAttributeMaxDynamicSharedMemorySize, SMEM_FUSED);
        attr_done = true;
    }

    zero_kernel<<<1, 32>>>();
    router_kernel<<<T_, 256>>>(x, gw);
    scan_scatter_kernel<<<1, 1024>>>();

    __half* sgwT; cudaGetSymbolAddress((void**)&sgwT, g_sgwT);
    __half* suwT; cudaGetSymbolAddress((void**)&suwT, g_suwT);
    __half* sdwT; cudaGetSymbolAddress((void**)&sdwT, g_sdwT);
    transpose_half<<<dim3(ISH_ / 32, H_ / 32), dim3(32, 8)>>>(sgw, sgwT, H_, ISH_);
    transpose_half<<<dim3(ISH_ / 32, H_ / 32), dim3(32, 8)>>>(suw, suwT, H_, ISH_);
    transpose_half<<<dim3(H_ / 32, ISH_ / 32), dim3(32, 8)>>>(sdw, sdwT, ISH_, H_);

    fused_gu_mma<<<NSH_GU + NEX_GU, 256, SMEM_FUSED>>>(gq, gz, gs, uq, uz, us);
    fused_dn_mma<<<NSH_DN + NEX_DN, 256, SMEM_FUSED>>>(dq, dz, ds, out);
    combine_kernel<<<T_, 256>>>(out);
}

// round 17
// speedup vs baseline: 1.2241x; 1.0113x over previous
#include <cuda_runtime.h>
#include <cuda_fp16.h>
#include <math.h>
#include <stdint.h>

#define E_    32
#define TOPK  4
#define H_    2048
#define I_    1408
#define GS_   128
#define T_    1024
#define ISH_  2816
#define NPAIR (T_*TOPK)

__device__ __forceinline__ int PERM(int i) {
    int r = i & 7;
    return (i & ~7) | (((r & 3) << 1) | (r >> 2));
}

// ---------------- device scratch ----------------
__device__ int    g_counts[E_];
__device__ int    g_offsets[E_];
__device__ int    g_cursor[E_];
__device__ int    g_topk_idx[T_][TOPK];
__device__ float  g_topk_w[T_][TOPK];
__device__ int    g_pair_token[NPAIR];
__device__ float  g_pair_w[NPAIR];
__device__ int    g_pair_pos[T_][TOPK];
__device__ __half g_xh[(size_t)T_ * H_];
__device__ __half g_h[(size_t)NPAIR * I_];
__device__ float  g_y[(size_t)NPAIR * H_];
__device__ __half g_sh[(size_t)T_ * ISH_];
__device__ __half g_sgwT[(size_t)ISH_ * H_];
__device__ __half g_suwT[(size_t)ISH_ * H_];
__device__ __half g_sdwT[(size_t)H_ * ISH_];

// ---------------- helpers ----------------
__device__ __forceinline__ uint32_t smem_u32(const void* p) {
    uint32_t a;
    asm("{ .reg .u64 t; cvta.to.shared.u64 t, %1; cvt.u32.u64 %0, t; }" : "=r"(a) : "l"(p));
    return a;
}
#define CP16(dst, src) asm volatile("cp.async.ca.shared.global [%0], [%1], 16;\n" :: "r"(dst), "l"(src))
#define CP_COMMIT()    asm volatile("cp.async.commit_group;\n" ::: "memory")
#define CP_WAIT0()     asm volatile("cp.async.wait_group 0;\n" ::: "memory")
#define CP_WAIT1()     asm volatile("cp.async.wait_group 1;\n" ::: "memory")
#define CP_WAIT2()     asm volatile("cp.async.wait_group 2;\n" ::: "memory")

__device__ __forceinline__ uint32_t dq2(uint32_t h, uint32_t z2, uint32_t s2) {
    __half2 r = __hmul2(__hsub2(*(__half2*)&h, *(__half2*)&z2), *(__half2*)&s2);
    return *(uint32_t*)&r;
}
__device__ __forceinline__ uint4 dqw_h(unsigned w, uint32_t z2, uint32_t s2) {
    uint4 v;
    v.x = dq2(( w        & 0x000F000Fu) | 0x64006400u, z2, s2);
    v.y = dq2(((w >> 4 ) & 0x000F000Fu) | 0x64006400u, z2, s2);
    v.z = dq2(((w >> 8 ) & 0x000F000Fu) | 0x64006400u, z2, s2);
    v.w = dq2(((w >> 12) & 0x000F000Fu) | 0x64006400u, z2, s2);
    return v;
}
__device__ __forceinline__ void mk_zs(int z, float s, uint32_t& z2, uint32_t& s2) {
    z2 = 0x64006400u | (unsigned)z | ((unsigned)z << 16);
    unsigned hb = __half_as_ushort(__float2half_rn(s));
    s2 = hb | (hb << 16);
}
__device__ __forceinline__ void mma16(float* d, const uint32_t* a, const uint32_t* b) {
    asm volatile("mma.sync.aligned.m16n8k16.row.col.f32.f16.f16.f32 "
        "{%0,%1,%2,%3},{%4,%5,%6,%7},{%8,%9},{%0,%1,%2,%3};\n"
        : "+f"(d[0]), "+f"(d[1]), "+f"(d[2]), "+f"(d[3])
        : "r"(a[0]), "r"(a[1]), "r"(a[2]), "r"(a[3]), "r"(b[0]), "r"(b[1]));
}
__device__ __forceinline__ float silu_mul(float g, float u) {
    return g / (1.f + __expf(-g)) * u;
}

// ======== expert layout (BM=64/BK=32): buffer = 5120 words, 4 buffers
#define BUFW3 5120
__device__ __forceinline__ int aoff3(int buf, int kf, int mf, int p) {
    return buf * BUFW3 + ((kf * 4 + mf) * 4 + p) * 32;
}
__device__ __forceinline__ int boff3gu(int buf, int kf, int sel, int nf, int r) {
    return buf * BUFW3 + 1024 + ((((kf * 2 + sel) * 16 + nf) * 2 + r)) * 32;
}
__device__ __forceinline__ int boff3dn(int buf, int kf, int nf, int r) {
    return buf * BUFW3 + 1024 + ((kf * 32 + nf) * 2 + r) * 32;
}
#define AUX3 (4 * BUFW3)

// ======== shared layout: buffer = 8192 words, 3 buffers
__device__ __forceinline__ int aoffw(int buf, int kf, int mf, int p) {
    return buf * 8192 + ((kf * 8 + mf) * 4 + p) * 32;
}
__device__ __forceinline__ int boffw_gu(int buf, int kf, int nf, int r, int sel) {
    return buf * 8192 + 4096 + sel * 2048 + ((kf * 8 + nf) * 2 + r) * 32;
}
__device__ __forceinline__ int boffw_dn(int buf, int kf, int nf, int r) {
    return buf * 8192 + 4096 + ((kf * 16 + nf) * 2 + r) * 32;
}
#define SMEM_FUSED ((3 * 8192 + 128) * 4)   // 98816 B; expert needs (4*5120+64)*4 = 82176 B < this

#define NSH_GU 352   // 44 x 8 shared_gu blocks
#define NEX_GU (11 * 16 * 32)
#define NSH_DN 128   // 16 x 8 shared_down blocks
#define NEX_DN (8 * 16 * 32)

// ---------------- small kernels ----------------
__global__ void zero_kernel() {
    int i = threadIdx.x;
    if (i < E_) g_counts[i] = 0;
}

__global__ void router_kernel(const float* __restrict__ x, const float* __restrict__ gw) {
    __shared__ float xs[H_];
    __shared__ float part[8][E_];
    __shared__ float scores[E_];
    int t = blockIdx.x;
    for (int h = threadIdx.x; h < H_; h += 256) {
        float v = x[t * H_ + h];
        xs[h] = v;
        g_xh[(size_t)t * H_ + PERM(h)] = __float2half_rn(v);
    }
    __syncthreads();
    int e = threadIdx.x & 31;
    int hh = threadIdx.x >> 5;
    float acc = 0.f;
    for (int h = hh; h < H_; h += 8) acc += xs[h] * gw[h * E_ + e];
    part[hh][e] = acc;
    __syncthreads();
    if (threadIdx.x < E_) {
        float s = 0.f;
        #pragma unroll
        for (int i = 0; i < 8; i++) s += part[i][threadIdx.x];
        scores[threadIdx.x] = 1.f / (1.f + expf(-s));
    }
    __syncthreads();
    if (threadIdx.x == 0) {
        bool used[E_];
        #pragma unroll
        for (int i = 0; i < E_; i++) used[i] = false;
        float v[TOPK]; int id[TOPK];
        float sum = 0.f;
        for (int j = 0; j < TOPK; j++) {
            float best = -1e30f; int bi = 0;
            for (int ee = 0; ee < E_; ee++)
                if (!used[ee] && scores[ee] > best) { best = scores[ee]; bi = ee; }
            used[bi] = true; v[j] = best; id[j] = bi; sum += best;
        }
        float inv = 2.5f / (sum + 1e-20f);
        for (int j = 0; j < TOPK; j++) {
            g_topk_idx[t][j] = id[j];
            g_topk_w[t][j] = v[j] * inv;
            atomicAdd(&g_counts[id[j]], 1);
        }
    }
}

__global__ void scan_scatter_kernel() {
    int tid = threadIdx.x;
    if (tid == 0) {
        int off = 0;
        for (int e = 0; e < E_; e++) {
            g_offsets[e] = off; g_cursor[e] = off; off += g_counts[e];
        }
    }
    __syncthreads();
    int t = tid;
    for (int j = 0; j < TOPK; j++) {
        int e = g_topk_idx[t][j];
        int pos = atomicAdd(&g_cursor[e], 1);
        g_pair_token[pos] = t;
        g_pair_w[pos] = g_topk_w[t][j];
        g_pair_pos[t][j] = pos;
    }
}

// single-launch transpose of all three shared weights, half2-vectorized PERM stores
#define NTB 5632   // blocks per matrix
__global__ void transpose_all(const float* __restrict__ sgw, const float* __restrict__ suw,
                              const float* __restrict__ sdw) {
    __shared__ float tile[32][33];
    int bid = blockIdx.x;
    int z = bid / NTB;
    int b = bid % NTB;
    const float* in; __half* out; int R, C, c0, r0;
    if (z < 2) {
        in = z ? suw : sgw;
        out = z ? g_suwT : g_sgwT;
        R = H_; C = ISH_;
        c0 = (b % 88) * 32;
        r0 = (b / 88) * 32;
    } else {
        in = sdw;
        out = g_sdwT;
        R = ISH_; C = H_;
        c0 = (b % 64) * 32;
        r0 = (b / 64) * 32;
    }
    for (int i = threadIdx.y; i < 32; i += 8)
        tile[i][threadIdx.x] = in[(size_t)(r0 + i) * C + c0 + threadIdx.x];
    __syncthreads();
    int tid = threadIdx.y * 32 + threadIdx.x;
    int hx = tid & 15, ibase = tid >> 4;
    int g = hx >> 2, q = hx & 3;
    #pragma unroll
    for (int ii = 0; ii < 2; ii++) {
        int i = ibase + ii * 16;
        __half2 h;
        h.x = __float2half_rn(tile[8 * g + q][i]);
        h.y = __float2half_rn(tile[8 * g + q + 4][i]);
        *(__half2*)&out[(size_t)(c0 + i) * R + r0 + 8 * g + 2 * q] = h;
    }
}

// final combine: out[t] += sum of 4 routed pair rows
__global__ void combine_kernel(float* __restrict__ out) {
    int t = blockIdx.x;
    int p0 = g_pair_pos[t][0], p1 = g_pair_pos[t][1];
    int p2 = g_pair_pos[t][2], p3 = g_pair_pos[t][3];
    const float* y0 = g_y + (size_t)p0 * H_;
    const float* y1 = g_y + (size_t)p1 * H_;
    const float* y2 = g_y + (size_t)p2 * H_;
    const float* y3 = g_y + (size_t)p3 * H_;
    float* orow = out + (size_t)t * H_;
    for (int c = threadIdx.x * 4; c < H_; c += 1024) {
        float4 o = *(float4*)(orow + c);
        float4 a = *(const float4*)(y0 + c);
        float4 b = *(const float4*)(y1 + c);
        float4 d = *(const float4*)(y2 + c);
        float4 e = *(const float4*)(y3 + c);
        o.x += a.x + b.x + d.x + e.x;
        o.y += a.y + b.y + d.y + e.y;
        o.z += a.z + b.z + d.z + e.z;
        o.w += a.w + b.w + d.w + e.w;
        *(float4*)(orow + c) = o;
    }
}

// ================= fused gate/up =================
__global__ __launch_bounds__(256, 2) void fused_gu_mma(
    const int* __restrict__ gq, const int* __restrict__ gz, const float* __restrict__ gs,
    const int* __restrict__ uq, const int* __restrict__ uz, const float* __restrict__ us)
{
    extern __shared__ uint32_t smw[];
    int bid = blockIdx.x;
    int tid = threadIdx.x;
    uint32_t smb = smem_u32(smw);

    if (bid < NSH_GU) {
        // ---------- shared gate/up: block 128M x 64N(per sel), 3-stage ----------
        int m0 = (bid / 44) * 128;
        int n0 = (bid % 44) * 64;

        int fm = tid & 127, kh = tid >> 7;
        const __half* xrow = g_xh + (size_t)(m0 + fm) * H_ + kh * 32;
        int amf = fm >> 4, ami8 = (fm & 15) >> 3, albA = 4 * (fm & 7);
        uint32_t adst[4];
        #pragma unroll
        for (int gg = 0; gg < 4; gg++)
            adst[gg] = smb + 4 * (aoffw(0, kh * 2 + (gg >> 1), amf, ami8 + 2 * (gg & 1)) + albA);

        int sel = tid >> 7;
        int t2 = tid & 127;
        int fn = t2 & 63, bkh = t2 >> 6;
        const __half* brow = (sel ? g_suwT : g_sgwT) + (size_t)(n0 + fn) * H_ + bkh * 32;
        int bnf = fn >> 3, blbB = 4 * (fn & 7);
        uint32_t bdst[4];
        #pragma unroll
        for (int wi = 0; wi < 4; wi++)
            bdst[wi] = smb + 4 * (boffw_gu(0, bkh * 2 + (wi >> 1), bnf, wi & 1, sel) + blbB);

        int w = tid >> 5, lane = tid & 31;
        int wm = w & 3, wn = w >> 2;

        float accG[2][4][4] = {};
        float accU[2][4][4] = {};

        const int NT = H_ / 64;
        #pragma unroll
        for (int s = 0; s < 2; s++) {
            uint32_t bo = s * 32768;
            #pragma unroll
            for (int gg = 0; gg < 4; gg++) {
                CP16(adst[gg] + bo, xrow + s * 64 + gg * 8);
                CP16(bdst[gg] + bo, brow + s * 64 + gg * 8);
            }
            CP_COMMIT();
        }
        CP_WAIT1();
        __syncthreads();

        int bufc = 0, bufn = 2;
        for (int t = 0; t < NT; t++) {
            if (t + 2 < NT) {
                uint32_t bo = bufn * 32768;
                const __half* xs = xrow + (t + 2) * 64;
                const __half* bs = brow + (t + 2) * 64;
                #pragma unroll
                for (int gg = 0; gg < 4; gg++) {
                    CP16(adst[gg] + bo, xs + gg * 8);
                    CP16(bdst[gg] + bo, bs + gg * 8);
                }
                CP_COMMIT();
            }
            #pragma unroll
            for (int kf = 0; kf < 4; kf++) {
                uint32_t a[2][4], bg[4][2], bu[4][2];
                #pragma unroll
                for (int mf = 0; mf < 2; mf++)
                    #pragma unroll
                    for (int r = 0; r < 4; r++)
                        a[mf][r] = smw[aoffw(bufc, kf, wm * 2 + mf, r) + lane];
                #pragma unroll
                for (int nf = 0; nf < 4; nf++)
                    #pragma unroll
                    for (int r = 0; r < 2; r++) {
                        bg[nf][r] = smw[boffw_gu(bufc, kf, wn * 4 + nf, r, 0) + lane];
                        bu[nf][r] = smw[boffw_gu(bufc, kf, wn * 4 + nf, r, 1) + lane];
                    }
                #pragma unroll
                for (int mf = 0; mf < 2; mf++)
                    #pragma unroll
                    for (int nf = 0; nf < 4; nf++) {
                        mma16(accG[mf][nf], a[mf], bg[nf]);
                        mma16(accU[mf][nf], a[mf], bu[nf]);
                    }
            }
            if (t + 1 < NT) {
                if (t + 2 < NT) CP_WAIT1(); else CP_WAIT0();
            }
            __syncthreads();
            bufc = (bufc == 2) ? 0 : bufc + 1;
            bufn = (bufn == 2) ? 0 : bufn + 1;
        }

        #pragma unroll
        for (int mf = 0; mf < 2; mf++) {
            #pragma unroll
            for (int hh = 0; hh < 2; hh++) {
                int row = wm * 32 + mf * 16 + (lane >> 2) + hh * 8;
                __half* orow = g_sh + (size_t)(m0 + row) * ISH_ + n0;
                #pragma unroll
                for (int nf = 0; nf < 4; nf++) {
                    int col = wn * 32 + nf * 8 + (lane & 3) * 2;
                    float vx = silu_mul(accG[mf][nf][hh * 2],     accU[mf][nf][hh * 2]);
                    float vy = silu_mul(accG[mf][nf][hh * 2 + 1], accU[mf][nf][hh * 2 + 1]);
                    int p = PERM(col);
                    orow[p]     = __float2half_rn(vx);
                    orow[p + 2] = __float2half_rn(vy);
                }
            }
        }
    } else {
        // ---------- expert gate/up: block 64M x 128N(per sel), 4-stage ----------
        int b = bid - NSH_GU;
        int e = b / 176;
        int r = b % 176;
        int m0 = (r / 11) * 64;
        int n0 = (r % 11) * 128;
        int cnt = g_counts[e];
        if (m0 >= cnt) return;
        int off = g_offsets[e];

        int* toks = (int*)&smw[AUX3];
        if (tid < 64) {
            int m = m0 + tid;
            toks[tid] = (m < cnt) ? g_pair_token[off + m] : 0;
        }
        __syncthreads();

        int fm = tid & 63, gsel = tid >> 6;
        const __half* xrow = g_xh + (size_t)toks[fm] * H_ + gsel * 8;
        uint32_t adst = smb + 4 * (aoff3(0, gsel >> 1, fm >> 4, ((fm & 15) >> 3) + 2 * (gsel & 1)) + 4 * (fm & 7));
        int sel = tid >> 7, fnl = tid & 127;
        long rowb = (long)e * I_ + n0 + fnl;
        const int4*  qr4 = (const int4*)((sel ? uq : gq) + rowb * (H_ / 8));
        const int*   zr  = (sel ? uz : gz) + rowb * (H_ / GS_);
        const float* sr  = (sel ? us : gs) + rowb * (H_ / GS_);
        int bnf = fnl >> 3, blbB = 4 * (fnl & 7);
        int bwi[4];
        #pragma unroll
        for (int wi = 0; wi < 4; wi++)
            bwi[wi] = boff3gu(0, wi >> 1, sel, bnf, wi & 1) + blbB;

        int wn = tid >> 5, lane = tid & 31;

        float accG[4][2][4] = {};
        float accU[4][2][4] = {};

        const int NT = H_ / 32;  // 64
        int4 pq_c, pq_n; uint32_t zc2, sc2, zn2, sn2;
        // prologue: A tiles 0,1,2 -> buf 0,1,2; B tiles 0,1 -> buf 0,1; pq_c=tile2, pq_n=tile3
        {
            uint32_t z02, s02; mk_zs(zr[0], sr[0], z02, s02);
            int4 q0 = qr4[0];
            CP16(adst, xrow); CP_COMMIT();
            unsigned w0[4] = {(unsigned)q0.x, (unsigned)q0.y, (unsigned)q0.z, (unsigned)q0.w};
            #pragma unroll
            for (int wi = 0; wi < 4; wi++) *(uint4*)&smw[bwi[wi]] = dqw_h(w0[wi], z02, s02);
            int4 q1 = qr4[1];
            CP16(adst + BUFW3 * 4, xrow + 32); CP_COMMIT();
            unsigned w1[4] = {(unsigned)q1.x, (unsigned)q1.y, (unsigned)q1.z, (unsigned)q1.w};
            #pragma unroll
            for (int wi = 0; wi < 4; wi++) *(uint4*)&smw[bwi[wi] + BUFW3] = dqw_h(w1[wi], z02, s02);
            CP16(adst + 2 * (BUFW3 * 4), xrow + 64); CP_COMMIT();
            pq_c = qr4[2]; zc2 = z02; sc2 = s02;   // tile2, group 0
            pq_n = qr4[3]; zn2 = z02; sn2 = s02;   // tile3, group 0
            CP_WAIT2();
            __syncthreads();
        }

        int bufc = 0;
        for (int t = 0; t < NT; t++) {
            if (t + 3 < NT) {
                CP16(adst + (uint32_t)((t + 3) & 3) * (BUFW3 * 4), xrow + (t + 3) * 32);
                CP_COMMIT();
            }
            if (t + 2 < NT) {
                int wo2 = ((t + 2) & 3) * BUFW3;
                unsigned wd[4] = {(unsigned)pq_c.x, (unsigned)pq_c.y, (unsigned)pq_c.z, (unsigned)pq_c.w};
                #pragma unroll
                for (int wi = 0; wi < 4; wi++) *(uint4*)&smw[bwi[wi] + wo2] = dqw_h(wd[wi], zc2, sc2);
                pq_c = pq_n; zc2 = zn2; sc2 = sn2;
                if (t + 4 < NT) {
                    int gi = (t + 4) >> 2;
                    pq_n = qr4[t + 4]; mk_zs(zr[gi], sr[gi], zn2, sn2);
                }
            }
            #pragma unroll
            for (int kf = 0; kf < 2; kf++) {
                uint32_t a[4][4], bg[2][2], bu[2][2];
                #pragma unroll
                for (int mf = 0; mf < 4; mf++)
                    #pragma unroll
                    for (int r = 0; r < 4; r++)
                        a[mf][r] = smw[aoff3(bufc, kf, mf, r) + lane];
                #pragma unroll
                for (int nf = 0; nf < 2; nf++)
                    #pragma unroll
                    for (int r = 0; r < 2; r++) {
                        bg[nf][r] = smw[boff3gu(bufc, kf, 0, wn * 2 + nf, r) + lane];
                        bu[nf][r] = smw[boff3gu(bufc, kf, 1, wn * 2 + nf, r) + lane];
                    }
                #pragma unroll
                for (int mf = 0; mf < 4; mf++)
                    #pragma unroll
                    for (int nf = 0; nf < 2; nf++) {
                        mma16(accG[mf][nf], a[mf], bg[nf]);
                        mma16(accU[mf][nf], a[mf], bu[nf]);
                    }
            }
            if (t + 1 < NT) {
                if (t + 3 < NT) CP_WAIT2();
                else if (t + 2 < NT) CP_WAIT1();
                else CP_WAIT0();
            }
            __syncthreads();
            bufc = (bufc + 1) & 3;
        }

        #pragma unroll
        for (int mf = 0; mf < 4; mf++) {
            #pragma unroll
            for (int hh = 0; hh < 2; hh++) {
                int row = mf * 16 + (lane >> 2) + hh * 8;
                if (m0 + row < cnt) {
                    __half* orow = g_h + (size_t)(off + m0 + row) * I_ + n0;
                    #pragma unroll
                    for (int nf = 0; nf < 2; nf++) {
                        int col = wn * 16 + nf * 8 + (lane & 3) * 2;
                        float vx = silu_mul(accG[mf][nf][hh * 2],     accU[mf][nf][hh * 2]);
                        float vy = silu_mul(accG[mf][nf][hh * 2 + 1], accU[mf][nf][hh * 2 + 1]);
                        int p = PERM(col);
                        orow[p]     = __float2half_rn(vx);
                        orow[p + 2] = __float2half_rn(vy);
                    }
                }
            }
        }
    }
}

// ================= fused down =================
__global__ __launch_bounds__(256, 2) void fused_dn_mma(
    const int* __restrict__ dq, const int* __restrict__ dz, const float* __restrict__ ds,
    float* __restrict__ out)
{
    extern __shared__ uint32_t smw[];
    int bid = blockIdx.x;
    int tid = threadIdx.x;
    uint32_t smb = smem_u32(smw);

    if (bid < NSH_DN) {
        // ---------- shared down: block 128M x 128N, 3-stage, writes out ----------
        int m0 = (bid / 16) * 128;
        int n0 = (bid % 16) * 128;

        int fm = tid & 127, kh = tid >> 7;
        const __half* arow = g_sh + (size_t)(m0 + fm) * ISH_ + kh * 32;
        int amf = fm >> 4, ami8 = (fm & 15) >> 3, albA = 4 * (fm & 7);
        uint32_t adst[4];
        #pragma unroll
        for (int gg = 0; gg < 4; gg++)
            adst[gg] = smb + 4 * (aoffw(0, kh * 2 + (gg >> 1), amf, ami8 + 2 * (gg & 1)) + albA);

        int fn = tid & 127, bkh = tid >> 7;
        const __half* brow = g_sdwT + (size_t)(n0 + fn) * ISH_ + bkh * 32;
        int bnf = fn >> 3, blbB = 4 * (fn & 7);
        uint32_t bdst[4];
        #pragma unroll
        for (int wi = 0; wi < 4; wi++)
            bdst[wi] = smb + 4 * (boffw_dn(0, bkh * 2 + (wi >> 1), bnf, wi & 1) + blbB);

        int w = tid >> 5, lane = tid & 31;
        int wm = w & 1, wn = w >> 1;

        float acc[4][4][4] = {};

        const int NT = ISH_ / 64;  // 44
        #pragma unroll
        for (int s = 0; s < 2; s++) {
            uint32_t bo = s * 32768;
            #pragma unroll
            for (int gg = 0; gg < 4; gg++) {
                CP16(adst[gg] + bo, arow + s * 64 + gg * 8);
                CP16(bdst[gg] + bo, brow + s * 64 + gg * 8);
            }
            CP_COMMIT();
        }
        CP_WAIT1();
        __syncthreads();

        int bufc = 0, bufn = 2;
        for (int t = 0; t < NT; t++) {
            if (t + 2 < NT) {
                uint32_t bo = bufn * 32768;
                const __half* as = arow + (t + 2) * 64;
                const __half* bs = brow + (t + 2) * 64;
                #pragma unroll
                for (int gg = 0; gg < 4; gg++) {
                    CP16(adst[gg] + bo, as + gg * 8);
                    CP16(bdst[gg] + bo, bs + gg * 8);
                }
                CP_COMMIT();
            }
            #pragma unroll
            for (int kf = 0; kf < 4; kf++) {
                uint32_t a[4][4], b[4][2];
                #pragma unroll
                for (int mf = 0; mf < 4; mf++)
                    #pragma unroll
                    for (int r = 0; r < 4; r++)
                        a[mf][r] = smw[aoffw(bufc, kf, wm * 4 + mf, r) + lane];
                #pragma unroll
                for (int nf = 0; nf < 4; nf++)
                    #pragma unroll
                    for (int r = 0; r < 2; r++)
                        b[nf][r] = smw[boffw_dn(bufc, kf, wn * 4 + nf, r) + lane];
                #pragma unroll
                for (int mf = 0; mf < 4; mf++)
                    #pragma unroll
                    for (int nf = 0; nf < 4; nf++)
                        mma16(acc[mf][nf], a[mf], b[nf]);
            }
            if (t + 1 < NT) {
                if (t + 2 < NT) CP_WAIT1(); else CP_WAIT0();
            }
            __syncthreads();
            bufc = (bufc == 2) ? 0 : bufc + 1;
            bufn = (bufn == 2) ? 0 : bufn + 1;
        }

        #pragma unroll
        for (int mf = 0; mf < 4; mf++) {
            #pragma unroll
            for (int hh = 0; hh < 2; hh++) {
                int row = wm * 64 + mf * 16 + (lane >> 2) + hh * 8;
                float* orow = out + (size_t)(m0 + row) * H_ + n0;
                #pragma unroll
                for (int nf = 0; nf < 4; nf++) {
                    int col = wn * 32 + nf * 8 + (lane & 3) * 2;
                    float2 v;
                    v.x = acc[mf][nf][hh * 2];
                    v.y = acc[mf][nf][hh * 2 + 1];
                    *(float2*)(orow + col) = v;
                }
            }
        }
    } else {
        // ---------- expert down: block 64M x 256N, 4-stage ----------
        int b = bid - NSH_DN;
        int e = b / 128;
        int r = b % 128;
        int m0 = (r / 8) * 64;
        int n0 = (r % 8) * 256;
        int cnt = g_counts[e];
        if (m0 >= cnt) return;
        int off = g_offsets[e];

        float* pwv = (float*)&smw[AUX3];
        if (tid < 64) {
            int m = m0 + tid;
            pwv[tid] = (m < cnt) ? g_pair_w[off + m] : 0.f;
        }
        __syncthreads();

        int fm = tid & 63, gsel = tid >> 6;
        size_t ar = (size_t)off + ((m0 + fm < cnt) ? (m0 + fm) : 0);
        const __half* hrow = g_h + ar * I_ + gsel * 8;
        uint32_t adst = smb + 4 * (aoff3(0, gsel >> 1, fm >> 4, ((fm & 15) >> 3) + 2 * (gsel & 1)) + 4 * (fm & 7));

        int fn = tid;
        long rowb = (long)e * H_ + n0 + fn;
        const int4*  qr4 = (const int4*)(dq + rowb * (I_ / 8));
        const int*   zr  = dz + rowb * (I_ / GS_);
        const float* sr  = ds + rowb * (I_ / GS_);
        int bnf = fn >> 3, blbB = 4 * (fn & 7);
        int bwi[4];
        #pragma unroll
        for (int wi = 0; wi < 4; wi++)
            bwi[wi] = boff3dn(0, wi >> 1, bnf, wi & 1) + blbB;

        int wn = tid >> 5, lane = tid & 31;

        float acc[4][4][4] = {};

        const int NT = I_ / 32;  // 44
        int4 pq_c, pq_n; uint32_t zc2, sc2, zn2, sn2;
        {
            uint32_t z02, s02; mk_zs(zr[0], sr[0], z02, s02);
            int4 q0 = qr4[0];
            CP16(adst, hrow); CP_COMMIT();
            unsigned w0[4] = {(unsigned)q0.x, (unsigned)q0.y, (unsigned)q0.z, (unsigned)q0.w};
            #pragma unroll
            for (int wi = 0; wi < 4; wi++) *(uint4*)&smw[bwi[wi]] = dqw_h(w0[wi], z02, s02);
            int4 q1 = qr4[1];
            CP16(adst + BUFW3 * 4, hrow + 32); CP_COMMIT();
            unsigned w1[4] = {(unsigned)q1.x, (unsigned)q1.y, (unsigned)q1.z, (unsigned)q1.w};
            #pragma unroll
            for (int wi = 0; wi < 4; wi++) *(uint4*)&smw[bwi[wi] + BUFW3] = dqw_h(w1[wi], z02, s02);
            CP16(adst + 2 * (BUFW3 * 4), hrow + 64); CP_COMMIT();
            pq_c = qr4[2]; zc2 = z02; sc2 = s02;
            pq_n = qr4[3]; zn2 = z02; sn2 = s02;
            CP_WAIT2();
            __syncthreads();
        }

        int bufc = 0;
        for (int t = 0; t < NT; t++) {
            if (t + 3 < NT) {
                CP16(adst + (uint32_t)((t + 3) & 3) * (BUFW3 * 4), hrow + (t + 3) * 32);
                CP_COMMIT();
            }
            if (t + 2 < NT) {
                int wo2 = ((t + 2) & 3) * BUFW3;
                unsigned wd[4] = {(unsigned)pq_c.x, (unsigned)pq_c.y, (unsigned)pq_c.z, (unsigned)pq_c.w};
                #pragma unroll
                for (int wi = 0; wi < 4; wi++) *(uint4*)&smw[bwi[wi] + wo2] = dqw_h(wd[wi], zc2, sc2);
                pq_c = pq_n; zc2 = zn2; sc2 = sn2;
                if (t + 4 < NT) {
                    int gi = (t + 4) >> 2;
                    pq_n = qr4[t + 4]; mk_zs(zr[gi], sr[gi], zn2, sn2);
                }
            }
            #pragma unroll
            for (int kf = 0; kf < 2; kf++) {
                uint32_t a[4][4], b[4][2];
                #pragma unroll
                for (int mf = 0; mf < 4; mf++)
                    #pragma unroll
                    for (int r = 0; r < 4; r++)
                        a[mf][r] = smw[aoff3(bufc, kf, mf, r) + lane];
                #pragma unroll
                for (int nf = 0; nf < 4; nf++)
                    #pragma unroll
                    for (int r = 0; r < 2; r++)
                        b[nf][r] = smw[boff3dn(bufc, kf, wn * 4 + nf, r) + lane];
                #pragma unroll
                for (int mf = 0; mf < 4; mf++)
                    #pragma unroll
                    for (int nf = 0; nf < 4; nf++)
                        mma16(acc[mf][nf], a[mf], b[nf]);
            }
            if (t + 1 < NT) {
                if (t + 3 < NT) CP_WAIT2();
                else if (t + 2 < NT) CP_WAIT1();
                else CP_WAIT0();
            }
            __syncthreads();
            bufc = (bufc + 1) & 3;
        }

        #pragma unroll
        for (int mf = 0; mf < 4; mf++) {
            #pragma unroll
            for (int hh = 0; hh < 2; hh++) {
                int row = mf * 16 + (lane >> 2) + hh * 8;
                if (m0 + row < cnt) {
                    float wgt = pwv[row];
                    float* orow = g_y + (size_t)(off + m0 + row) * H_ + n0;
                    #pragma unroll
                    for (int nf = 0; nf < 4; nf++) {
                        int col = wn * 32 + nf * 8 + (lane & 3) * 2;
                        float2 v;
                        v.x = wgt * acc[mf][nf][hh * 2];
                        v.y = wgt * acc[mf][nf][hh * 2 + 1];
                        *(float2*)(orow + col) = v;
                    }
                }
            }
        }
    }
}

// ---------------- launch ----------------
extern "C" void kernel_launch(void* const* d_in, const int* in_sizes, int n_in,
                              void* d_out, int out_size)
{
    const float* x   = (const float*)d_in[0];
    const float* gw  = (const float*)d_in[1];
    const int*   gq  = (const int*)  d_in[2];
    const int*   gz  = (const int*)  d_in[3];
    const float* gs  = (const float*)d_in[4];
    const int*   uq  = (const int*)  d_in[5];
    const int*   uz  = (const int*)  d_in[6];
    const float* us  = (const float*)d_in[7];
    const int*   dq  = (const int*)  d_in[8];
    const int*   dz  = (const int*)  d_in[9];
    const float* ds  = (const float*)d_in[10];
    const float* sgw = (const float*)d_in[11];
    const float* suw = (const float*)d_in[12];
    const float* sdw = (const float*)d_in[13];
    float* out = (float*)d_out;

    static bool attr_done = false;
    if (!attr_done) {
        cudaFuncSetAttribute(fused_gu_mma, cudaFuncAttributeMaxDynamicSharedMemorySize, SMEM_FUSED);
        cudaFuncSetAttribute(fused_dn_mma, cudaFuncAttributeMaxDynamicSharedMemorySize, SMEM_FUSED);
        attr_done = true;
    }

    zero_kernel<<<1, 32>>>();
    router_kernel<<<T_, 256>>>(x, gw);
    scan_scatter_kernel<<<1, 1024>>>();

    transpose_all<<<3 * NTB, dim3(32, 8)>>>(sgw, suw, sdw);

    fused_gu_mma<<<NSH_GU + NEX_GU, 256, SMEM_FUSED>>>(gq, gz, gs, uq, uz, us);
    fused_dn_mma<<<NSH_DN + NEX_DN, 256, SMEM_FUSED>>>(dq, dz, ds, out);
    combine_kernel<<<T_, 256>>>(out);
}